// round 3
// baseline (speedup 1.0000x reference)
#include <cuda_runtime.h>
#include <cstdint>

#define BATCH 4
#define NHEAD 8
#define S_LEN 2048
#define FDIM  1024
#define DHEAD 128
#define ZTOT  (BATCH*NHEAD)

// ---------------- scratch (no allocations allowed) ----------------
static __device__ float g_sig[4];
static __device__ float g_v1[4][FDIM];
static __device__ float g_s1[4][FDIM];
static __device__ __align__(128) float g_q[(size_t)ZTOT*S_LEN*DHEAD];
static __device__ __align__(128) float g_k[(size_t)ZTOT*S_LEN*DHEAD];
static __device__ __align__(128) float g_v[(size_t)ZTOT*S_LEN*DHEAD];
static __device__ __align__(128) float g_ctx[(size_t)BATCH*S_LEN*FDIM];
static __device__ __align__(128) float2 g_stats[(size_t)ZTOT*S_LEN*16]; // per (z,row,nblk): {max, sumexp}
static __device__ float g_rowM[(size_t)ZTOT*S_LEN];
static __device__ float g_rowI[(size_t)ZTOT*S_LEN];   // 1/Z

// ---------------- helpers ----------------
__device__ __forceinline__ float warp_sum(float v){
    #pragma unroll
    for (int o=16;o;o>>=1) v += __shfl_xor_sync(0xffffffffu, v, o);
    return v;
}
__device__ __forceinline__ uint32_t f2tf(float x){
    uint32_t r; asm("cvt.rna.tf32.f32 %0, %1;" : "=r"(r) : "f"(x)); return r;
}
template<bool X3>
__device__ __forceinline__ void splitf(float f, uint32_t& h, uint32_t& l){
    h = f2tf(f);
    if (X3) l = f2tf(f - __uint_as_float(h));
}
__device__ __forceinline__ void mma8(float* c, const uint32_t* a, const uint32_t* b){
    asm volatile(
        "mma.sync.aligned.m16n8k8.row.col.f32.tf32.tf32.f32 "
        "{%0,%1,%2,%3},{%4,%5,%6,%7},{%8,%9},{%0,%1,%2,%3};\n"
        : "+f"(c[0]), "+f"(c[1]), "+f"(c[2]), "+f"(c[3])
        : "r"(a[0]), "r"(a[1]), "r"(a[2]), "r"(a[3]), "r"(b[0]), "r"(b[1]));
}
__device__ __forceinline__ void cp16(void* s, const void* g){
    uint32_t sa = (uint32_t)__cvta_generic_to_shared(s);
    asm volatile("cp.async.cg.shared.global [%0], [%1], 16;\n" :: "r"(sa), "l"(g));
}

// ---------------- spectral norm (exact fp32) ----------------
__global__ void k_sigma_v(const float* w0,const float* w1,const float* w2,const float* w3,
                          const float* u0,const float* u1,const float* u2,const float* u3){
    const float* Wt[4]={w0,w1,w2,w3};
    const float* Ut[4]={u0,u1,u2,u3};
    int wi = blockIdx.y;
    const float* W = Wt[wi];
    const float* U = Ut[wi];
    int lane = threadIdx.x&31, warp = threadIdx.x>>5;
    int row = blockIdx.x*8 + warp;
    const float* r = W + (size_t)row*FDIM;
    float acc = 0.f;
    for (int j=lane;j<FDIM;j+=32) acc += U[j]*r[j];
    acc = warp_sum(acc);
    if (!lane) g_v1[wi][row] = acc;
}
__global__ void k_sigma_s(const float* w0,const float* w1,const float* w2,const float* w3){
    const float* Wt[4]={w0,w1,w2,w3};
    int wi = blockIdx.y;
    const float* W = Wt[wi];
    int o = blockIdx.x*256 + threadIdx.x;
    float acc = 0.f;
    for (int i=0;i<FDIM;i++) acc += g_v1[wi][i]*W[(size_t)i*FDIM+o];
    g_s1[wi][o] = acc;
}
__global__ void k_sigma_fin(){
    __shared__ float rv[8], rs[8];
    int wi = blockIdx.x, tid = threadIdx.x;
    float sv=0.f, ss=0.f;
    for (int i=tid;i<FDIM;i+=256){
        float a=g_v1[wi][i]; sv += a*a;
        float b=g_s1[wi][i]; ss += b*b;
    }
    sv = warp_sum(sv); ss = warp_sum(ss);
    if ((tid&31)==0){ rv[tid>>5]=sv; rs[tid>>5]=ss; }
    __syncthreads();
    if (tid==0){
        float a=0.f,b=0.f;
        for (int i=0;i<8;i++){ a+=rv[i]; b+=rs[i]; }
        g_sig[wi] = sqrtf(a/b);
    }
}

// ---------------- cp.async double-buffered tf32(x3) GEMM ----------------
// C(MxN)=A(MxK)*B. CTA 128x128, k-tile 32, 8 warps (2x4), warp tile 64x32.
// smem holds raw fp32 tiles (double buffered); tf32 hi/lo split at frag load.
// BLAY==0: B[K,N] n-contig.  BLAY==1: B[N,K] k-contig (C = A B^T).
// EPI: 0 = QK logits -> Dst + z*S*S, + per-(row,nblk) softmax stats to g_stats
//      1 = proj: v*sig + bias, head-split write to [B,H,S,D]
//      3 = out:  x0 + (v*sig + bias)*gamma
template<int EPI, bool X3, int BLAY>
__global__ void __launch_bounds__(256) gemm_async(
    const float* __restrict__ A0, const float* __restrict__ B0,
    float* __restrict__ Dst, int K, int lda, int ldb,
    const float* __restrict__ sig, const float* __restrict__ bias,
    const float* __restrict__ x0, const float* __restrict__ gammap)
{
    constexpr int ASZ = 128*36;
    constexpr int BSZ = (BLAY==1) ? 128*36 : 32*136;
    extern __shared__ float sm[];
    float* Abuf[2] = { sm,        sm + (ASZ+BSZ) };
    float* Bbuf[2] = { sm + ASZ,  sm + (ASZ+BSZ) + ASZ };

    const int tid = threadIdx.x;
    const int lane = tid & 31;
    const int warp = tid >> 5;
    const int wm = warp >> 2;
    const int wn = warp & 3;
    const int rl = lane >> 2;
    const int cl = lane & 3;
    const int z = blockIdx.z;
    const int mblk = blockIdx.y * 128;
    const int nblk = blockIdx.x * 128;

    const float* Ag = A0;
    const float* Bg = B0;
    if (EPI==0){ Ag += (size_t)z*S_LEN*DHEAD; Bg += (size_t)z*S_LEN*DHEAD; }
    Ag += (size_t)mblk * lda;
    Bg += (BLAY==1) ? (size_t)nblk*ldb : (size_t)nblk;

    float acc[4][4][4];
    #pragma unroll
    for (int i=0;i<4;i++)
        #pragma unroll
        for (int j=0;j<4;j++)
            #pragma unroll
            for (int r=0;r<4;r++) acc[i][j][r]=0.f;

    const int nkt = K >> 5;

    // issue tile 0
    {
        #pragma unroll
        for (int i=0;i<4;i++){
            int idx = tid + i*256;
            cp16(&Abuf[0][(idx>>3)*36 + ((idx&7)<<2)], Ag + (size_t)(idx>>3)*lda + ((idx&7)<<2));
        }
        #pragma unroll
        for (int i=0;i<4;i++){
            int idx = tid + i*256;
            if (BLAY==1)
                cp16(&Bbuf[0][(idx>>3)*36 + ((idx&7)<<2)], Bg + (size_t)(idx>>3)*ldb + ((idx&7)<<2));
            else
                cp16(&Bbuf[0][(idx>>5)*136 + ((idx&31)<<2)], Bg + (size_t)(idx>>5)*ldb + ((idx&31)<<2));
        }
        asm volatile("cp.async.commit_group;\n" ::: "memory");
    }

    for (int kt=0; kt<nkt; kt++){
        asm volatile("cp.async.wait_group 0;\n" ::: "memory");
        __syncthreads();
        if (kt+1 < nkt){
            Ag += 32;
            Bg += (BLAY==1) ? 32 : (size_t)32*ldb;
            float* An = Abuf[(kt+1)&1];
            float* Bn = Bbuf[(kt+1)&1];
            #pragma unroll
            for (int i=0;i<4;i++){
                int idx = tid + i*256;
                cp16(&An[(idx>>3)*36 + ((idx&7)<<2)], Ag + (size_t)(idx>>3)*lda + ((idx&7)<<2));
            }
            #pragma unroll
            for (int i=0;i<4;i++){
                int idx = tid + i*256;
                if (BLAY==1)
                    cp16(&Bn[(idx>>3)*36 + ((idx&7)<<2)], Bg + (size_t)(idx>>3)*ldb + ((idx&7)<<2));
                else
                    cp16(&Bn[(idx>>5)*136 + ((idx&31)<<2)], Bg + (size_t)(idx>>5)*ldb + ((idx&31)<<2));
            }
            asm volatile("cp.async.commit_group;\n" ::: "memory");
        }
        const float* Ac = Abuf[kt&1];
        const float* Bc = Bbuf[kt&1];

        #pragma unroll
        for (int ks=0; ks<4; ks++){
            const int kb = ks*8;
            uint32_t ah[4][4], al[4][4], bh[4][2], bl[4][2];
            #pragma unroll
            for (int mt=0; mt<4; mt++){
                int base = (wm*64 + mt*16 + rl)*36 + kb + cl;
                float f0 = Ac[base];
                float f1 = Ac[base + 288];
                float f2 = Ac[base + 4];
                float f3 = Ac[base + 292];
                splitf<X3>(f0, ah[mt][0], al[mt][0]);
                splitf<X3>(f1, ah[mt][1], al[mt][1]);
                splitf<X3>(f2, ah[mt][2], al[mt][2]);
                splitf<X3>(f3, ah[mt][3], al[mt][3]);
            }
            #pragma unroll
            for (int nt=0; nt<4; nt++){
                float g0, g1;
                if (BLAY==1){
                    int base = (wn*32 + nt*8 + rl)*36 + kb + cl;
                    g0 = Bc[base]; g1 = Bc[base + 4];
                } else {
                    int base = (kb + cl)*136 + wn*32 + nt*8 + rl;
                    g0 = Bc[base]; g1 = Bc[base + 544];
                }
                splitf<X3>(g0, bh[nt][0], bl[nt][0]);
                splitf<X3>(g1, bh[nt][1], bl[nt][1]);
            }
            #pragma unroll
            for (int mt=0; mt<4; mt++)
                #pragma unroll
                for (int nt=0; nt<4; nt++){
                    mma8(acc[mt][nt], ah[mt], bh[nt]);
                    if (X3){
                        mma8(acc[mt][nt], ah[mt], bl[nt]);
                        mma8(acc[mt][nt], al[mt], bh[nt]);
                    }
                }
        }
    }

    // ---- epilogue ----
    float sg = 1.f, gm = 1.f;
    if (EPI==1 || EPI==3) sg = *sig;
    if (EPI==3) gm = *gammap;
    #pragma unroll
    for (int mt=0; mt<4; mt++){
        #pragma unroll
        for (int nt=0; nt<4; nt++){
            int row0 = mblk + wm*64 + mt*16 + rl;
            int col  = nblk + wn*32 + nt*8 + 2*cl;
            #pragma unroll
            for (int h2=0; h2<2; h2++){
                int row = row0 + h2*8;
                float v0 = acc[mt][nt][h2*2+0];
                float v1 = acc[mt][nt][h2*2+1];
                if (EPI==0){
                    *reinterpret_cast<float2*>(Dst + (size_t)z*S_LEN*S_LEN + (size_t)row*S_LEN + col)
                        = make_float2(v0, v1);
                } else if (EPI==1){
                    float o0 = v0*sg + bias[col];
                    float o1 = v1*sg + bias[col+1];
                    int b = row >> 11, s = row & (S_LEN-1);
                    int h = col >> 7, d = col & (DHEAD-1);
                    *reinterpret_cast<float2*>(Dst + (((size_t)(b*NHEAD+h)*S_LEN + s)*DHEAD + d))
                        = make_float2(o0, o1);
                } else {
                    size_t idx = (size_t)row*FDIM + col;
                    float o0 = x0[idx]   + (v0*sg + bias[col])*gm;
                    float o1 = x0[idx+1] + (v1*sg + bias[col+1])*gm;
                    *reinterpret_cast<float2*>(Dst + idx) = make_float2(o0, o1);
                }
            }
        }
    }

    // ---- QK softmax stats: per-(row, 128-col block) online (max, sumexp) ----
    if constexpr (EPI==0){
        __shared__ float sMx[4][128];
        __shared__ float sSm[4][128];
        #pragma unroll
        for (int mt=0; mt<4; mt++){
            #pragma unroll
            for (int h2=0; h2<2; h2++){
                float m = acc[mt][0][h2*2];
                #pragma unroll
                for (int nt=0; nt<4; nt++){
                    m = fmaxf(m, acc[mt][nt][h2*2+0]);
                    m = fmaxf(m, acc[mt][nt][h2*2+1]);
                }
                float s = 0.f;
                #pragma unroll
                for (int nt=0; nt<4; nt++){
                    s += __expf(acc[mt][nt][h2*2+0] - m);
                    s += __expf(acc[mt][nt][h2*2+1] - m);
                }
                #pragma unroll
                for (int off=1; off<4; off<<=1){
                    float om = __shfl_xor_sync(0xffffffffu, m, off);
                    float os = __shfl_xor_sync(0xffffffffu, s, off);
                    float nm = fmaxf(m, om);
                    s = s*__expf(m-nm) + os*__expf(om-nm);
                    m = nm;
                }
                if (cl==0){
                    int rloc = wm*64 + mt*16 + h2*8 + rl;
                    sMx[wn][rloc] = m;
                    sSm[wn][rloc] = s;
                }
            }
        }
        __syncthreads();
        if (tid < 128){
            float M = sMx[0][tid], S = sSm[0][tid];
            #pragma unroll
            for (int w=1; w<4; w++){
                float m2 = sMx[w][tid], s2 = sSm[w][tid];
                float nm = fmaxf(M, m2);
                S = S*__expf(M-nm) + s2*__expf(m2-nm);
                M = nm;
            }
            g_stats[((size_t)z*S_LEN + mblk + tid)*16 + blockIdx.x] = make_float2(M, S);
        }
    }
}

// ---------------- merge per-block stats -> per-row (M, 1/Z) ----------------
__global__ void k_merge(){
    size_t r = (size_t)blockIdx.x*256 + threadIdx.x;
    const float2* st = g_stats + r*16;
    float2 p0 = st[0];
    float M = p0.x, S = p0.y;
    #pragma unroll
    for (int i=1;i<16;i++){
        float2 p = st[i];
        float nm = fmaxf(M, p.x);
        S = S*__expf(M-nm) + p.y*__expf(p.x-nm);
        M = nm;
    }
    g_rowM[r] = M;
    g_rowI[r] = 1.f/S;
}

// ---------------- AV GEMM with fused softmax-normalize + attn writeback ----
// ctx[z] = softmax(logits[z]) @ v[z]. Reads raw logits, computes p inline,
// writes p back in place (each element read by exactly one CTA), tf32 x1.
__global__ void __launch_bounds__(256) gemm_av(
    float* __restrict__ attn,            // raw logits in, probs out (in-place)
    const float* __restrict__ Bv,        // g_v [Z][S][D]
    float* __restrict__ Dst)             // g_ctx [B][S][F]
{
    constexpr int ASZ = 128*36;
    constexpr int BSZ = 32*136;
    extern __shared__ uint32_t smu[];
    uint32_t* Ah = smu;
    uint32_t* Bh = smu + ASZ;
    __shared__ float sM[128], sI[128];

    const int tid = threadIdx.x;
    const int lane = tid & 31;
    const int warp = tid >> 5;
    const int wm = warp >> 2;
    const int wn = warp & 3;
    const int rl = lane >> 2;
    const int cl = lane & 3;
    const int z = blockIdx.z;
    const int mblk = blockIdx.y * 128;

    if (tid < 128){
        sM[tid] = g_rowM[(size_t)z*S_LEN + mblk + tid];
        sI[tid] = g_rowI[(size_t)z*S_LEN + mblk + tid];
    }

    const float* Ag = attn + (size_t)z*S_LEN*S_LEN + (size_t)mblk*S_LEN;
    float*       Aw = attn + (size_t)z*S_LEN*S_LEN + (size_t)mblk*S_LEN;
    const float* Bg = Bv   + (size_t)z*S_LEN*DHEAD;

    float acc[4][4][4];
    #pragma unroll
    for (int i=0;i<4;i++)
        #pragma unroll
        for (int j=0;j<4;j++)
            #pragma unroll
            for (int r=0;r<4;r++) acc[i][j][r]=0.f;

    const int nkt = S_LEN >> 5;   // 64
    float4 ra[4], rb[4];
    #pragma unroll
    for (int i=0;i<4;i++){
        int idx = tid + i*256;
        ra[i] = *reinterpret_cast<const float4*>(Ag + (size_t)(idx>>3)*S_LEN + ((idx&7)<<2));
        rb[i] = *reinterpret_cast<const float4*>(Bg + (size_t)(idx>>5)*DHEAD + ((idx&31)<<2));
    }

    for (int kt=0; kt<nkt; kt++){
        __syncthreads();
        #pragma unroll
        for (int i=0;i<4;i++){
            int idx = tid + i*256;
            {
                int row = idx>>3;
                int kk  = (idx&7)<<2;
                float M = sM[row], inv = sI[row];
                float4 v = ra[i];
                float4 p;
                p.x = __expf(v.x - M)*inv;
                p.y = __expf(v.y - M)*inv;
                p.z = __expf(v.z - M)*inv;
                p.w = __expf(v.w - M)*inv;
                int base = row*36 + kk;
                *reinterpret_cast<uint4*>(&Ah[base]) =
                    make_uint4(f2tf(p.x), f2tf(p.y), f2tf(p.z), f2tf(p.w));
                *reinterpret_cast<float4*>(Aw + (size_t)row*S_LEN + kt*32 + kk) = p;
            }
            {
                int base = (idx>>5)*136 + ((idx&31)<<2);
                float4 v = rb[i];
                *reinterpret_cast<uint4*>(&Bh[base]) =
                    make_uint4(f2tf(v.x), f2tf(v.y), f2tf(v.z), f2tf(v.w));
            }
        }
        __syncthreads();
        Ag += 32;
        Bg += (size_t)32*DHEAD;
        if (kt+1 < nkt){
            #pragma unroll
            for (int i=0;i<4;i++){
                int idx = tid + i*256;
                ra[i] = *reinterpret_cast<const float4*>(Ag + (size_t)(idx>>3)*S_LEN + ((idx&7)<<2));
                rb[i] = *reinterpret_cast<const float4*>(Bg + (size_t)(idx>>5)*DHEAD + ((idx&31)<<2));
            }
        }
        #pragma unroll
        for (int ks=0; ks<4; ks++){
            const int kb = ks*8;
            uint32_t ah[4][4], bh[4][2];
            #pragma unroll
            for (int mt=0; mt<4; mt++){
                int base = (wm*64 + mt*16 + rl)*36 + kb + cl;
                ah[mt][0]=Ah[base];     ah[mt][1]=Ah[base+288];
                ah[mt][2]=Ah[base+4];   ah[mt][3]=Ah[base+292];
            }
            #pragma unroll
            for (int nt=0; nt<4; nt++){
                int base = (kb + cl)*136 + wn*32 + nt*8 + rl;
                bh[nt][0]=Bh[base]; bh[nt][1]=Bh[base+544];
            }
            #pragma unroll
            for (int mt=0; mt<4; mt++)
                #pragma unroll
                for (int nt=0; nt<4; nt++)
                    mma8(acc[mt][nt], ah[mt], bh[nt]);
        }
    }

    // epilogue: merged-head ctx write
    const int b = z >> 3, h = z & 7;
    #pragma unroll
    for (int mt=0; mt<4; mt++){
        #pragma unroll
        for (int nt=0; nt<4; nt++){
            int row0 = mblk + wm*64 + mt*16 + rl;
            int col  = wn*32 + nt*8 + 2*cl;
            #pragma unroll
            for (int h2=0; h2<2; h2++){
                int row = row0 + h2*8;
                *reinterpret_cast<float2*>(Dst + ((size_t)b*S_LEN + row)*FDIM + h*DHEAD + col)
                    = make_float2(acc[mt][nt][h2*2+0], acc[mt][nt][h2*2+1]);
            }
        }
    }
}

// ---------------- launch ----------------
extern "C" void kernel_launch(void* const* d_in, const int* in_sizes, int n_in,
                              void* d_out, int out_size)
{
    (void)in_sizes; (void)n_in; (void)out_size;
    const float* x  = (const float*)d_in[0];
    const float* wq = (const float*)d_in[1];
    const float* bq = (const float*)d_in[2];
    const float* uq = (const float*)d_in[3];
    const float* wk = (const float*)d_in[4];
    const float* bk = (const float*)d_in[5];
    const float* uk = (const float*)d_in[6];
    const float* wv = (const float*)d_in[7];
    const float* bv = (const float*)d_in[8];
    const float* uv = (const float*)d_in[9];
    const float* wo = (const float*)d_in[10];
    const float* bo = (const float*)d_in[11];
    const float* uo = (const float*)d_in[12];
    const float* gm = (const float*)d_in[13];

    float* out  = (float*)d_out;
    float* attn = out + (size_t)BATCH*S_LEN*FDIM;

    float *pq,*pk,*pv,*pctx,*psig;
    cudaGetSymbolAddress((void**)&pq,   g_q);
    cudaGetSymbolAddress((void**)&pk,   g_k);
    cudaGetSymbolAddress((void**)&pv,   g_v);
    cudaGetSymbolAddress((void**)&pctx, g_ctx);
    cudaGetSymbolAddress((void**)&psig, g_sig);

    cudaFuncSetAttribute(gemm_async<1,true ,0>, cudaFuncAttributeMaxDynamicSharedMemorySize, 71680);
    cudaFuncSetAttribute(gemm_async<1,false,0>, cudaFuncAttributeMaxDynamicSharedMemorySize, 71680);
    cudaFuncSetAttribute(gemm_async<3,false,0>, cudaFuncAttributeMaxDynamicSharedMemorySize, 71680);
    cudaFuncSetAttribute(gemm_async<0,true ,1>, cudaFuncAttributeMaxDynamicSharedMemorySize, 73728);

    // spectral norms (exact fp32)
    k_sigma_v<<<dim3(128,4),256>>>(wq,wk,wv,wo, uq,uk,uv,uo);
    k_sigma_s<<<dim3(4,4),256>>>(wq,wk,wv,wo);
    k_sigma_fin<<<4,256>>>();

    // projections: q,k fp32-class (feed softmax), v single-tf32 (only affects out)
    gemm_async<1,true ,0><<<dim3(8,64,1),256,71680>>>(x, wq, pq, FDIM, FDIM, FDIM, psig+0, bq, nullptr, nullptr);
    gemm_async<1,true ,0><<<dim3(8,64,1),256,71680>>>(x, wk, pk, FDIM, FDIM, FDIM, psig+1, bk, nullptr, nullptr);
    gemm_async<1,false,0><<<dim3(8,64,1),256,71680>>>(x, wv, pv, FDIM, FDIM, FDIM, psig+2, bv, nullptr, nullptr);

    // logits = q k^T (tf32x3) + per-block softmax stats
    gemm_async<0,true ,1><<<dim3(16,16,32),256,73728>>>(pq, pk, attn, DHEAD, DHEAD, DHEAD,
                                                        nullptr,nullptr,nullptr,nullptr);
    // merge stats -> per-row (M, 1/Z)
    k_merge<<<(ZTOT*S_LEN)/256,256>>>();

    // ctx = softmax(logits) @ v, normalize inline, write probs in place
    gemm_av<<<dim3(1,16,32),256,35840>>>(attn, pv, pctx);

    // out = x + (ctx @ wo_n + bo) * gamma (single-tf32)
    gemm_async<3,false,0><<<dim3(8,64,1),256,71680>>>(pctx, wo, out, FDIM, FDIM, FDIM, psig+3, bo, x, gm);
}

// round 6
// speedup vs baseline: 1.1580x; 1.1580x over previous
#include <cuda_runtime.h>
#include <cstdint>

#define BATCH 4
#define NHEAD 8
#define S_LEN 2048
#define FDIM  1024
#define DHEAD 128
#define ZTOT  (BATCH*NHEAD)
#define NTOK  (BATCH*S_LEN)

// ---------------- scratch (no allocations allowed) ----------------
static __device__ float g_sig[4];
static __device__ float g_v1[4][FDIM];
static __device__ float g_s1[4][FDIM];
// pre-split tf32 operands
static __device__ __align__(128) uint32_t g_xh[(size_t)NTOK*FDIM];
static __device__ __align__(128) uint32_t g_xl[(size_t)NTOK*FDIM];
static __device__ __align__(128) uint32_t g_wh[4][(size_t)FDIM*FDIM];
static __device__ __align__(128) uint32_t g_wl[4][(size_t)FDIM*FDIM];
static __device__ __align__(128) uint32_t g_qh[(size_t)ZTOT*S_LEN*DHEAD];
static __device__ __align__(128) uint32_t g_ql[(size_t)ZTOT*S_LEN*DHEAD];
static __device__ __align__(128) uint32_t g_kh[(size_t)ZTOT*S_LEN*DHEAD];
static __device__ __align__(128) uint32_t g_kl[(size_t)ZTOT*S_LEN*DHEAD];
static __device__ __align__(128) uint32_t g_vh[(size_t)ZTOT*S_LEN*DHEAD];
static __device__ __align__(128) uint32_t g_ctxh[(size_t)NTOK*FDIM];
static __device__ __align__(128) float2 g_stats[(size_t)ZTOT*S_LEN*16];
static __device__ float g_rowM[(size_t)ZTOT*S_LEN];
static __device__ float g_rowI[(size_t)ZTOT*S_LEN];

// ---------------- helpers ----------------
__device__ __forceinline__ float warp_sum(float v){
    #pragma unroll
    for (int o=16;o;o>>=1) v += __shfl_xor_sync(0xffffffffu, v, o);
    return v;
}
__device__ __forceinline__ uint32_t f2tf(float x){
    uint32_t r; asm("cvt.rna.tf32.f32 %0, %1;" : "=r"(r) : "f"(x)); return r;
}
__device__ __forceinline__ void mma8(float* c, const uint32_t* a, const uint32_t* b){
    asm volatile(
        "mma.sync.aligned.m16n8k8.row.col.f32.tf32.tf32.f32 "
        "{%0,%1,%2,%3},{%4,%5,%6,%7},{%8,%9},{%0,%1,%2,%3};\n"
        : "+f"(c[0]), "+f"(c[1]), "+f"(c[2]), "+f"(c[3])
        : "r"(a[0]), "r"(a[1]), "r"(a[2]), "r"(a[3]), "r"(b[0]), "r"(b[1]));
}
__device__ __forceinline__ void cp16(void* s, const void* g){
    uint32_t sa = (uint32_t)__cvta_generic_to_shared(s);
    asm volatile("cp.async.cg.shared.global [%0], [%1], 16;\n" :: "r"(sa), "l"(g));
}

// ---------------- tf32 hi/lo pre-split ----------------
__global__ void __launch_bounds__(256) k_split(const float4* __restrict__ src,
                                               uint4* __restrict__ hi,
                                               uint4* __restrict__ lo, int n4){
    int i = blockIdx.x*256 + threadIdx.x;
    if (i >= n4) return;
    float4 v = src[i];
    uint32_t h0=f2tf(v.x), h1=f2tf(v.y), h2=f2tf(v.z), h3=f2tf(v.w);
    hi[i] = make_uint4(h0,h1,h2,h3);
    lo[i] = make_uint4(f2tf(v.x-__uint_as_float(h0)), f2tf(v.y-__uint_as_float(h1)),
                       f2tf(v.z-__uint_as_float(h2)), f2tf(v.w-__uint_as_float(h3)));
}

// ---------------- spectral norm (exact fp32) ----------------
__global__ void k_sigma_v(const float* w0,const float* w1,const float* w2,const float* w3,
                          const float* u0,const float* u1,const float* u2,const float* u3){
    const float* Wt[4]={w0,w1,w2,w3};
    const float* Ut[4]={u0,u1,u2,u3};
    int wi = blockIdx.y;
    const float* W = Wt[wi];
    const float* U = Ut[wi];
    int lane = threadIdx.x&31, warp = threadIdx.x>>5;
    int row = blockIdx.x*8 + warp;
    const float* r = W + (size_t)row*FDIM;
    float acc = 0.f;
    for (int j=lane;j<FDIM;j+=32) acc += U[j]*r[j];
    acc = warp_sum(acc);
    if (!lane) g_v1[wi][row] = acc;
}
__global__ void k_sigma_s(const float* w0,const float* w1,const float* w2,const float* w3){
    const float* Wt[4]={w0,w1,w2,w3};
    int wi = blockIdx.y;
    const float* W = Wt[wi];
    int o = blockIdx.x*256 + threadIdx.x;
    float acc = 0.f;
    for (int i=0;i<FDIM;i++) acc += g_v1[wi][i]*W[(size_t)i*FDIM+o];
    g_s1[wi][o] = acc;
}
__global__ void k_sigma_fin(){
    __shared__ float rv[8], rs[8];
    int wi = blockIdx.x, tid = threadIdx.x;
    float sv=0.f, ss=0.f;
    for (int i=tid;i<FDIM;i+=256){
        float a=g_v1[wi][i]; sv += a*a;
        float b=g_s1[wi][i]; ss += b*b;
    }
    sv = warp_sum(sv); ss = warp_sum(ss);
    if ((tid&31)==0){ rv[tid>>5]=sv; rs[tid>>5]=ss; }
    __syncthreads();
    if (tid==0){
        float a=0.f,b=0.f;
        for (int i=0;i<8;i++){ a+=rv[i]; b+=rs[i]; }
        g_sig[wi] = sqrtf(a/b);
    }
}

// ---------------- pre-split cp.async double-buffered tf32(x3) GEMM ----------
// Operands arrive already tf32-split in global memory. Hot loop = cp.async+LDS+MMA.
// CTA 128x128, k-tile 32, 8 warps (2x4), warp tile 64x32.
// EPI==0 (QK, BLAY=1): C=A B^T, Dst=fp32 logits + per-(row,nblk) stats.
// EPI==1 (proj, BLAY=0): o=v*sig+bias, head-split write: X3 -> Dh,Dl ; else Dh.
// EPI==3 (out,  BLAY=0): Dst = x0 + (v*sig+bias)*gamma.
template<int EPI, bool X3>
__global__ void __launch_bounds__(256) gemm_pre(
    const uint32_t* __restrict__ Ah0, const uint32_t* __restrict__ Al0,
    const uint32_t* __restrict__ Bh0, const uint32_t* __restrict__ Bl0,
    float* __restrict__ Dst, uint32_t* __restrict__ Dh, uint32_t* __restrict__ Dl,
    int K, int lda, int ldb,
    const float* __restrict__ sig, const float* __restrict__ bias,
    const float* __restrict__ x0, const float* __restrict__ gammap)
{
    constexpr int BLAY = (EPI==0) ? 1 : 0;
    constexpr int ASZ = 128*36;
    constexpr int BSZ = (BLAY==1) ? 128*36 : 32*136;
    constexpr int NA  = X3 ? 2 : 1;
    constexpr int STRIDE = NA*ASZ + NA*BSZ;
    extern __shared__ uint32_t sm[];

    const int tid = threadIdx.x;
    const int lane = tid & 31;
    const int warp = tid >> 5;
    const int wm = warp >> 2;
    const int wn = warp & 3;
    const int rl = lane >> 2;
    const int cl = lane & 3;
    const int z = blockIdx.z;
    const int mblk = blockIdx.y * 128;
    const int nblk = blockIdx.x * 128;

    const uint32_t* Agh = Ah0;
    const uint32_t* Agl = Al0;
    const uint32_t* Bgh = Bh0;
    const uint32_t* Bgl = Bl0;
    if (EPI==0){
        Agh += (size_t)z*S_LEN*DHEAD; Agl += (size_t)z*S_LEN*DHEAD;
        Bgh += (size_t)z*S_LEN*DHEAD; Bgl += (size_t)z*S_LEN*DHEAD;
    }
    Agh += (size_t)mblk*lda;  Agl += (size_t)mblk*lda;
    if (BLAY==1){ Bgh += (size_t)nblk*ldb; Bgl += (size_t)nblk*ldb; }
    else        { Bgh += nblk;             Bgl += nblk; }

    float acc[4][4][4];
    #pragma unroll
    for (int i=0;i<4;i++)
        #pragma unroll
        for (int j=0;j<4;j++)
            #pragma unroll
            for (int r=0;r<4;r++) acc[i][j][r]=0.f;

    const int nkt = K >> 5;

    auto issue = [&](int buf){
        uint32_t* Abh = sm + buf*STRIDE;
        uint32_t* Abl = Abh + ASZ;
        uint32_t* Bbh = Abh + NA*ASZ;
        uint32_t* Bbl = Bbh + BSZ;
        #pragma unroll
        for (int i=0;i<4;i++){
            int idx = tid + i*256;
            int off = (idx>>3)*36 + ((idx&7)<<2);
            size_t gsrc = (size_t)(idx>>3)*lda + ((idx&7)<<2);
            cp16(&Abh[off], Agh + gsrc);
            if (X3) cp16(&Abl[off], Agl + gsrc);
        }
        #pragma unroll
        for (int i=0;i<4;i++){
            int idx = tid + i*256;
            if (BLAY==1){
                int off = (idx>>3)*36 + ((idx&7)<<2);
                size_t gsrc = (size_t)(idx>>3)*ldb + ((idx&7)<<2);
                cp16(&Bbh[off], Bgh + gsrc);
                if (X3) cp16(&Bbl[off], Bgl + gsrc);
            } else {
                int off = (idx>>5)*136 + ((idx&31)<<2);
                size_t gsrc = (size_t)(idx>>5)*ldb + ((idx&31)<<2);
                cp16(&Bbh[off], Bgh + gsrc);
                if (X3) cp16(&Bbl[off], Bgl + gsrc);
            }
        }
        asm volatile("cp.async.commit_group;\n" ::: "memory");
    };

    issue(0);

    for (int kt=0; kt<nkt; kt++){
        asm volatile("cp.async.wait_group 0;\n" ::: "memory");
        __syncthreads();
        if (kt+1 < nkt){
            Agh += 32; Agl += 32;
            if (BLAY==1){ Bgh += 32; Bgl += 32; }
            else        { Bgh += (size_t)32*ldb; Bgl += (size_t)32*ldb; }
            issue((kt+1)&1);
        }
        const uint32_t* Ach = sm + (kt&1)*STRIDE;
        const uint32_t* Acl = Ach + ASZ;
        const uint32_t* Bch = Ach + NA*ASZ;
        const uint32_t* Bcl = Bch + BSZ;

        #pragma unroll
        for (int ks=0; ks<4; ks++){
            const int kb = ks*8;
            uint32_t ah[4][4], al[4][4], bh[4][2], bl[4][2];
            #pragma unroll
            for (int mt=0; mt<4; mt++){
                int base = (wm*64 + mt*16 + rl)*36 + kb + cl;
                ah[mt][0]=Ach[base];     ah[mt][1]=Ach[base+288];
                ah[mt][2]=Ach[base+4];   ah[mt][3]=Ach[base+292];
                if (X3){
                    al[mt][0]=Acl[base];     al[mt][1]=Acl[base+288];
                    al[mt][2]=Acl[base+4];   al[mt][3]=Acl[base+292];
                }
            }
            #pragma unroll
            for (int nt=0; nt<4; nt++){
                if (BLAY==1){
                    int base = (wn*32 + nt*8 + rl)*36 + kb + cl;
                    bh[nt][0]=Bch[base]; bh[nt][1]=Bch[base+4];
                    if (X3){ bl[nt][0]=Bcl[base]; bl[nt][1]=Bcl[base+4]; }
                } else {
                    int base = (kb + cl)*136 + wn*32 + nt*8 + rl;
                    bh[nt][0]=Bch[base]; bh[nt][1]=Bch[base+544];
                    if (X3){ bl[nt][0]=Bcl[base]; bl[nt][1]=Bcl[base+544]; }
                }
            }
            #pragma unroll
            for (int mt=0; mt<4; mt++)
                #pragma unroll
                for (int nt=0; nt<4; nt++){
                    mma8(acc[mt][nt], ah[mt], bh[nt]);
                    if (X3){
                        mma8(acc[mt][nt], ah[mt], bl[nt]);
                        mma8(acc[mt][nt], al[mt], bh[nt]);
                    }
                }
        }
    }

    // ---- epilogue ----
    float sg = 1.f, gm = 1.f;
    if (EPI==1 || EPI==3) sg = *sig;
    if (EPI==3) gm = *gammap;
    #pragma unroll
    for (int mt=0; mt<4; mt++){
        #pragma unroll
        for (int nt=0; nt<4; nt++){
            int row0 = mblk + wm*64 + mt*16 + rl;
            int col  = nblk + wn*32 + nt*8 + 2*cl;
            #pragma unroll
            for (int h2=0; h2<2; h2++){
                int row = row0 + h2*8;
                float v0 = acc[mt][nt][h2*2+0];
                float v1 = acc[mt][nt][h2*2+1];
                if (EPI==0){
                    *reinterpret_cast<float2*>(Dst + (size_t)z*S_LEN*S_LEN + (size_t)row*S_LEN + col)
                        = make_float2(v0, v1);
                } else if (EPI==1){
                    float o0 = v0*sg + bias[col];
                    float o1 = v1*sg + bias[col+1];
                    int b = row >> 11, s = row & (S_LEN-1);
                    int h = col >> 7, d = col & (DHEAD-1);
                    size_t o = (((size_t)(b*NHEAD+h))*S_LEN + s)*DHEAD + d;
                    uint32_t h0 = f2tf(o0), h1 = f2tf(o1);
                    *reinterpret_cast<uint2*>(Dh + o) = make_uint2(h0, h1);
                    if (X3){
                        *reinterpret_cast<uint2*>(Dl + o) =
                            make_uint2(f2tf(o0-__uint_as_float(h0)), f2tf(o1-__uint_as_float(h1)));
                    }
                } else {
                    size_t idx = (size_t)row*FDIM + col;
                    float o0 = x0[idx]   + (v0*sg + bias[col])*gm;
                    float o1 = x0[idx+1] + (v1*sg + bias[col+1])*gm;
                    *reinterpret_cast<float2*>(Dst + idx) = make_float2(o0, o1);
                }
            }
        }
    }

    // ---- QK softmax stats ----
    if constexpr (EPI==0){
        __shared__ float sMx[4][128];
        __shared__ float sSm[4][128];
        #pragma unroll
        for (int mt=0; mt<4; mt++){
            #pragma unroll
            for (int h2=0; h2<2; h2++){
                float m = acc[mt][0][h2*2];
                #pragma unroll
                for (int nt=0; nt<4; nt++){
                    m = fmaxf(m, acc[mt][nt][h2*2+0]);
                    m = fmaxf(m, acc[mt][nt][h2*2+1]);
                }
                float s = 0.f;
                #pragma unroll
                for (int nt=0; nt<4; nt++){
                    s += __expf(acc[mt][nt][h2*2+0] - m);
                    s += __expf(acc[mt][nt][h2*2+1] - m);
                }
                #pragma unroll
                for (int off=1; off<4; off<<=1){
                    float om = __shfl_xor_sync(0xffffffffu, m, off);
                    float os = __shfl_xor_sync(0xffffffffu, s, off);
                    float nm = fmaxf(m, om);
                    s = s*__expf(m-nm) + os*__expf(om-nm);
                    m = nm;
                }
                if (cl==0){
                    int rloc = wm*64 + mt*16 + h2*8 + rl;
                    sMx[wn][rloc] = m;
                    sSm[wn][rloc] = s;
                }
            }
        }
        __syncthreads();
        if (tid < 128){
            float M = sMx[0][tid], S = sSm[0][tid];
            #pragma unroll
            for (int w=1; w<4; w++){
                float m2 = sMx[w][tid], s2 = sSm[w][tid];
                float nm = fmaxf(M, m2);
                S = S*__expf(M-nm) + s2*__expf(m2-nm);
                M = nm;
            }
            g_stats[((size_t)z*S_LEN + mblk + tid)*16 + blockIdx.x] = make_float2(M, S);
        }
    }
}

// ---------------- merge per-block stats -> per-row (M, 1/Z) ----------------
__global__ void k_merge(){
    size_t r = (size_t)blockIdx.x*256 + threadIdx.x;
    const float2* st = g_stats + r*16;
    float2 p0 = st[0];
    float M = p0.x, S = p0.y;
    #pragma unroll
    for (int i=1;i<16;i++){
        float2 p = st[i];
        float nm = fmaxf(M, p.x);
        S = S*__expf(M-nm) + p.y*__expf(p.x-nm);
        M = nm;
    }
    g_rowM[r] = M;
    g_rowI[r] = 1.f/S;
}

// ---------------- AV GEMM: fused softmax-normalize + attn writeback --------
__global__ void __launch_bounds__(256) gemm_av(
    float* __restrict__ attn,               // raw logits in, probs out
    const uint32_t* __restrict__ Bv,        // g_vh [Z][S][D] tf32
    uint32_t* __restrict__ Dst)             // g_ctxh [B][S][F] tf32
{
    constexpr int ASZ = 128*36;
    extern __shared__ uint32_t smu[];
    uint32_t* Ah = smu;
    uint32_t* Bh = smu + ASZ;
    __shared__ float sM[128], sI[128];

    const int tid = threadIdx.x;
    const int lane = tid & 31;
    const int warp = tid >> 5;
    const int wm = warp >> 2;
    const int wn = warp & 3;
    const int rl = lane >> 2;
    const int cl = lane & 3;
    const int z = blockIdx.z;
    const int mblk = blockIdx.y * 128;

    if (tid < 128){
        sM[tid] = g_rowM[(size_t)z*S_LEN + mblk + tid];
        sI[tid] = g_rowI[(size_t)z*S_LEN + mblk + tid];
    }

    const float*    Ag = attn + (size_t)z*S_LEN*S_LEN + (size_t)mblk*S_LEN;
    float*          Aw = attn + (size_t)z*S_LEN*S_LEN + (size_t)mblk*S_LEN;
    const uint32_t* Bg = Bv   + (size_t)z*S_LEN*DHEAD;

    float acc[4][4][4];
    #pragma unroll
    for (int i=0;i<4;i++)
        #pragma unroll
        for (int j=0;j<4;j++)
            #pragma unroll
            for (int r=0;r<4;r++) acc[i][j][r]=0.f;

    const int nkt = S_LEN >> 5;
    float4 ra[4];
    uint4  rb[4];
    #pragma unroll
    for (int i=0;i<4;i++){
        int idx = tid + i*256;
        ra[i] = *reinterpret_cast<const float4*>(Ag + (size_t)(idx>>3)*S_LEN + ((idx&7)<<2));
        rb[i] = *reinterpret_cast<const uint4*>(Bg + (size_t)(idx>>5)*DHEAD + ((idx&31)<<2));
    }

    for (int kt=0; kt<nkt; kt++){
        __syncthreads();
        #pragma unroll
        for (int i=0;i<4;i++){
            int idx = tid + i*256;
            {
                int row = idx>>3;
                int kk  = (idx&7)<<2;
                float M = sM[row], inv = sI[row];
                float4 v = ra[i];
                float4 p;
                p.x = __expf(v.x - M)*inv;
                p.y = __expf(v.y - M)*inv;
                p.z = __expf(v.z - M)*inv;
                p.w = __expf(v.w - M)*inv;
                *reinterpret_cast<uint4*>(&Ah[row*36 + kk]) =
                    make_uint4(f2tf(p.x), f2tf(p.y), f2tf(p.z), f2tf(p.w));
                *reinterpret_cast<float4*>(Aw + (size_t)row*S_LEN + kt*32 + kk) = p;
            }
            *reinterpret_cast<uint4*>(&Bh[(idx>>5)*136 + ((idx&31)<<2)]) = rb[i];
        }
        __syncthreads();
        Ag += 32;
        Bg += (size_t)32*DHEAD;
        if (kt+1 < nkt){
            #pragma unroll
            for (int i=0;i<4;i++){
                int idx = tid + i*256;
                ra[i] = *reinterpret_cast<const float4*>(Ag + (size_t)(idx>>3)*S_LEN + ((idx&7)<<2));
                rb[i] = *reinterpret_cast<const uint4*>(Bg + (size_t)(idx>>5)*DHEAD + ((idx&31)<<2));
            }
        }
        #pragma unroll
        for (int ks=0; ks<4; ks++){
            const int kb = ks*8;
            uint32_t ah[4][4], bh[4][2];
            #pragma unroll
            for (int mt=0; mt<4; mt++){
                int base = (wm*64 + mt*16 + rl)*36 + kb + cl;
                ah[mt][0]=Ah[base];     ah[mt][1]=Ah[base+288];
                ah[mt][2]=Ah[base+4];   ah[mt][3]=Ah[base+292];
            }
            #pragma unroll
            for (int nt=0; nt<4; nt++){
                int base = (kb + cl)*136 + wn*32 + nt*8 + rl;
                bh[nt][0]=Bh[base]; bh[nt][1]=Bh[base+544];
            }
            #pragma unroll
            for (int mt=0; mt<4; mt++)
                #pragma unroll
                for (int nt=0; nt<4; nt++)
                    mma8(acc[mt][nt], ah[mt], bh[nt]);
        }
    }

    const int b = z >> 3, h = z & 7;
    #pragma unroll
    for (int mt=0; mt<4; mt++){
        #pragma unroll
        for (int nt=0; nt<4; nt++){
            int row0 = mblk + wm*64 + mt*16 + rl;
            int col  = wn*32 + nt*8 + 2*cl;
            #pragma unroll
            for (int h2=0; h2<2; h2++){
                int row = row0 + h2*8;
                *reinterpret_cast<uint2*>(Dst + ((size_t)b*S_LEN + row)*FDIM + h*DHEAD + col)
                    = make_uint2(f2tf(acc[mt][nt][h2*2+0]), f2tf(acc[mt][nt][h2*2+1]));
            }
        }
    }
}

// ---------------- launch ----------------
extern "C" void kernel_launch(void* const* d_in, const int* in_sizes, int n_in,
                              void* d_out, int out_size)
{
    (void)in_sizes; (void)n_in; (void)out_size;
    const float* x  = (const float*)d_in[0];
    const float* wq = (const float*)d_in[1];
    const float* bq = (const float*)d_in[2];
    const float* uq = (const float*)d_in[3];
    const float* wk = (const float*)d_in[4];
    const float* bk = (const float*)d_in[5];
    const float* uk = (const float*)d_in[6];
    const float* wv = (const float*)d_in[7];
    const float* bv = (const float*)d_in[8];
    const float* uv = (const float*)d_in[9];
    const float* wo = (const float*)d_in[10];
    const float* bo = (const float*)d_in[11];
    const float* uo = (const float*)d_in[12];
    const float* gm = (const float*)d_in[13];

    float* out  = (float*)d_out;
    float* attn = out + (size_t)NTOK*FDIM;

    uint32_t *pxh,*pxl,*pwh,*pwl,*pqh,*pql,*pkh,*pkl,*pvh,*pctxh;
    float *psig;
    cudaGetSymbolAddress((void**)&pxh,  g_xh);
    cudaGetSymbolAddress((void**)&pxl,  g_xl);
    cudaGetSymbolAddress((void**)&pwh,  g_wh);
    cudaGetSymbolAddress((void**)&pwl,  g_wl);
    cudaGetSymbolAddress((void**)&pqh,  g_qh);
    cudaGetSymbolAddress((void**)&pql,  g_ql);
    cudaGetSymbolAddress((void**)&pkh,  g_kh);
    cudaGetSymbolAddress((void**)&pkl,  g_kl);
    cudaGetSymbolAddress((void**)&pvh,  g_vh);
    cudaGetSymbolAddress((void**)&pctxh,g_ctxh);
    cudaGetSymbolAddress((void**)&psig, g_sig);

    cudaFuncSetAttribute(gemm_pre<1,true >, cudaFuncAttributeMaxDynamicSharedMemorySize, 143360);
    cudaFuncSetAttribute(gemm_pre<1,false>, cudaFuncAttributeMaxDynamicSharedMemorySize, 71680);
    cudaFuncSetAttribute(gemm_pre<3,false>, cudaFuncAttributeMaxDynamicSharedMemorySize, 71680);
    cudaFuncSetAttribute(gemm_pre<0,true >, cudaFuncAttributeMaxDynamicSharedMemorySize, 147456);
    cudaFuncSetAttribute(gemm_av,           cudaFuncAttributeMaxDynamicSharedMemorySize, 35840);

    const size_t WSZ = (size_t)FDIM*FDIM;

    // spectral norms (exact fp32) + operand pre-splits
    k_sigma_v<<<dim3(128,4),256>>>(wq,wk,wv,wo, uq,uk,uv,uo);
    k_sigma_s<<<dim3(4,4),256>>>(wq,wk,wv,wo);
    k_sigma_fin<<<4,256>>>();
    k_split<<<(NTOK*FDIM/4+255)/256,256>>>((const float4*)x, (uint4*)pxh, (uint4*)pxl, NTOK*FDIM/4);
    k_split<<<(WSZ/4+255)/256,256>>>((const float4*)wq, (uint4*)(pwh+0*WSZ), (uint4*)(pwl+0*WSZ), WSZ/4);
    k_split<<<(WSZ/4+255)/256,256>>>((const float4*)wk, (uint4*)(pwh+1*WSZ), (uint4*)(pwl+1*WSZ), WSZ/4);
    k_split<<<(WSZ/4+255)/256,256>>>((const float4*)wv, (uint4*)(pwh+2*WSZ), (uint4*)(pwl+2*WSZ), WSZ/4);
    k_split<<<(WSZ/4+255)/256,256>>>((const float4*)wo, (uint4*)(pwh+3*WSZ), (uint4*)(pwl+3*WSZ), WSZ/4);

    // projections: q,k fp32-class x3 (write hi+lo), v single-tf32 (hi only)
    gemm_pre<1,true ><<<dim3(8,64,1),256,143360>>>(pxh,pxl, pwh+0*WSZ,pwl+0*WSZ,
        nullptr, pqh, pql, FDIM, FDIM, FDIM, psig+0, bq, nullptr, nullptr);
    gemm_pre<1,true ><<<dim3(8,64,1),256,143360>>>(pxh,pxl, pwh+1*WSZ,pwl+1*WSZ,
        nullptr, pkh, pkl, FDIM, FDIM, FDIM, psig+1, bk, nullptr, nullptr);
    gemm_pre<1,false><<<dim3(8,64,1),256,71680>>>(pxh,nullptr, pwh+2*WSZ,nullptr,
        nullptr, pvh, nullptr, FDIM, FDIM, FDIM, psig+2, bv, nullptr, nullptr);

    // logits = q k^T (x3) + stats
    gemm_pre<0,true ><<<dim3(16,16,32),256,147456>>>(pqh,pql, pkh,pkl,
        attn, nullptr, nullptr, DHEAD, DHEAD, DHEAD, nullptr, nullptr, nullptr, nullptr);
    k_merge<<<(ZTOT*S_LEN)/256,256>>>();

    // ctx = softmax(logits) @ v (x1), probs written in place, ctx as tf32
    gemm_av<<<dim3(1,16,32),256,35840>>>(attn, pvh, pctxh);

    // out = x + (ctx @ wo + bo) * gamma (x1)
    gemm_pre<3,false><<<dim3(8,64,1),256,71680>>>(pctxh,nullptr, pwh+3*WSZ,nullptr,
        out, nullptr, nullptr, FDIM, FDIM, FDIM, psig+3, bo, x, gm);
}

// round 7
// speedup vs baseline: 1.2165x; 1.0506x over previous
#include <cuda_runtime.h>
#include <cstdint>

#define BATCH 4
#define NHEAD 8
#define S_LEN 2048
#define FDIM  1024
#define DHEAD 128
#define ZTOT  (BATCH*NHEAD)
#define NTOK  (BATCH*S_LEN)
#define QSZ   ((size_t)ZTOT*S_LEN*DHEAD)
#define WSZE  ((size_t)FDIM*FDIM)

// ---------------- scratch (no allocations allowed) ----------------
static __device__ float g_sig[4];
static __device__ float g_v1[4][FDIM];
static __device__ float g_s1[4][FDIM];
static __device__ __align__(128) uint32_t g_xh[(size_t)NTOK*FDIM];
static __device__ __align__(128) uint32_t g_xl[(size_t)NTOK*FDIM];
static __device__ __align__(128) uint32_t g_wh[4][WSZE];
static __device__ __align__(128) uint32_t g_wl[4][WSZE];
static __device__ __align__(128) uint32_t g_qkh[2*QSZ];   // q then k
static __device__ __align__(128) uint32_t g_qkl[2*QSZ];
static __device__ __align__(128) uint32_t g_vh[QSZ];
static __device__ __align__(128) uint32_t g_ctxh[(size_t)NTOK*FDIM];
static __device__ __align__(128) float2 g_stats[(size_t)ZTOT*S_LEN*16];
static __device__ float g_rowM[(size_t)ZTOT*S_LEN];
static __device__ float g_rowI[(size_t)ZTOT*S_LEN];

// ---------------- helpers ----------------
__device__ __forceinline__ float warp_sum(float v){
    #pragma unroll
    for (int o=16;o;o>>=1) v += __shfl_xor_sync(0xffffffffu, v, o);
    return v;
}
__device__ __forceinline__ uint32_t f2tf(float x){
    uint32_t r; asm("cvt.rna.tf32.f32 %0, %1;" : "=r"(r) : "f"(x)); return r;
}
__device__ __forceinline__ void mma8(float* c, const uint32_t* a, const uint32_t* b){
    asm volatile(
        "mma.sync.aligned.m16n8k8.row.col.f32.tf32.tf32.f32 "
        "{%0,%1,%2,%3},{%4,%5,%6,%7},{%8,%9},{%0,%1,%2,%3};\n"
        : "+f"(c[0]), "+f"(c[1]), "+f"(c[2]), "+f"(c[3])
        : "r"(a[0]), "r"(a[1]), "r"(a[2]), "r"(a[3]), "r"(b[0]), "r"(b[1]));
}
__device__ __forceinline__ void cp16(void* s, const void* g){
    uint32_t sa = (uint32_t)__cvta_generic_to_shared(s);
    asm volatile("cp.async.cg.shared.global [%0], [%1], 16;\n" :: "r"(sa), "l"(g));
}

// ---------------- merged tf32 hi/lo pre-split (x + 4 weights) -------------
__global__ void __launch_bounds__(256) k_split_all(
    const float4* __restrict__ x,
    const float4* __restrict__ w0, const float4* __restrict__ w1,
    const float4* __restrict__ w2, const float4* __restrict__ w3,
    uint4* __restrict__ xh, uint4* __restrict__ xl,
    uint4* __restrict__ wh, uint4* __restrict__ wl)
{
    const int NXB = (NTOK*FDIM/4)/256;       // 8192 blocks for x
    const int NWB = (int)(WSZE/4)/256;       // 1024 blocks per weight
    int b = blockIdx.x;
    const float4* src; uint4 *hi, *lo; size_t i;
    if (b < NXB){
        src = x; hi = xh; lo = xl;
        i = (size_t)b*256 + threadIdx.x;
    } else {
        int s   = (b - NXB) / NWB;
        int off = (b - NXB) % NWB;
        const float4* ws[4] = {w0,w1,w2,w3};
        src = ws[s];
        hi = wh + s*(WSZE/4);
        lo = wl + s*(WSZE/4);
        i = (size_t)off*256 + threadIdx.x;
    }
    float4 v = src[i];
    uint32_t h0=f2tf(v.x), h1=f2tf(v.y), h2=f2tf(v.z), h3=f2tf(v.w);
    hi[i] = make_uint4(h0,h1,h2,h3);
    lo[i] = make_uint4(f2tf(v.x-__uint_as_float(h0)), f2tf(v.y-__uint_as_float(h1)),
                       f2tf(v.z-__uint_as_float(h2)), f2tf(v.w-__uint_as_float(h3)));
}

// ---------------- spectral norm (exact fp32) ----------------
__global__ void k_sigma_v(const float* w0,const float* w1,const float* w2,const float* w3,
                          const float* u0,const float* u1,const float* u2,const float* u3){
    const float* Wt[4]={w0,w1,w2,w3};
    const float* Ut[4]={u0,u1,u2,u3};
    int wi = blockIdx.y;
    const float* W = Wt[wi];
    const float* U = Ut[wi];
    int lane = threadIdx.x&31, warp = threadIdx.x>>5;
    int row = blockIdx.x*8 + warp;
    const float* r = W + (size_t)row*FDIM;
    float acc = 0.f;
    for (int j=lane;j<FDIM;j+=32) acc += U[j]*r[j];
    acc = warp_sum(acc);
    if (!lane) g_v1[wi][row] = acc;
}
__global__ void k_sigma_s(const float* w0,const float* w1,const float* w2,const float* w3){
    const float* Wt[4]={w0,w1,w2,w3};
    int wi = blockIdx.y;
    const float* W = Wt[wi];
    int o = blockIdx.x*256 + threadIdx.x;
    float acc = 0.f;
    for (int i=0;i<FDIM;i++) acc += g_v1[wi][i]*W[(size_t)i*FDIM+o];
    g_s1[wi][o] = acc;
}
__global__ void k_sigma_fin(){
    __shared__ float rv[8], rs[8];
    int wi = blockIdx.x, tid = threadIdx.x;
    float sv=0.f, ss=0.f;
    for (int i=tid;i<FDIM;i+=256){
        float a=g_v1[wi][i]; sv += a*a;
        float b=g_s1[wi][i]; ss += b*b;
    }
    sv = warp_sum(sv); ss = warp_sum(ss);
    if ((tid&31)==0){ rv[tid>>5]=sv; rs[tid>>5]=ss; }
    __syncthreads();
    if (tid==0){
        float a=0.f,b=0.f;
        for (int i=0;i<8;i++){ a+=rv[i]; b+=rs[i]; }
        g_sig[wi] = sqrtf(a/b);
    }
}

// ---------------- pre-split cp.async double-buffered tf32(x3) GEMM ----------
// CTA 128x128, k-tile 32, 8 warps (2x4), warp tile 64x32. Hot loop: cp.async+LDS+MMA.
// EPI==0 (QK, BLAY=1): C=A B^T, logits + per-(row,nblk) stats. z = head.
// EPI==1 (proj, BLAY=0): z selects weight/bias/out (merged q,k or single v).
// EPI==3 (out,  BLAY=0): Dst = x0 + (v*sig+bias)*gamma.
template<int EPI, bool X3, int MINCTA>
__global__ void __launch_bounds__(256, MINCTA) gemm_pre(
    const uint32_t* __restrict__ Ah0, const uint32_t* __restrict__ Al0,
    const uint32_t* __restrict__ Bh0, const uint32_t* __restrict__ Bl0,
    float* __restrict__ Dst, uint32_t* __restrict__ Dh, uint32_t* __restrict__ Dl,
    int K, int lda, int ldb,
    const float* __restrict__ sig, const float* __restrict__ bias,
    const float* __restrict__ bias2,
    const float* __restrict__ x0, const float* __restrict__ gammap)
{
    constexpr int BLAY = (EPI==0) ? 1 : 0;
    constexpr int ASZ = 128*36;
    constexpr int BSZ = (BLAY==1) ? 128*36 : 32*136;
    constexpr int NA  = X3 ? 2 : 1;
    constexpr int STRIDE = NA*ASZ + NA*BSZ;
    extern __shared__ uint32_t sm[];

    const int tid = threadIdx.x;
    const int lane = tid & 31;
    const int warp = tid >> 5;
    const int wm = warp >> 2;
    const int wn = warp & 3;
    const int rl = lane >> 2;
    const int cl = lane & 3;
    const int z = blockIdx.z;
    const int mblk = blockIdx.y * 128;
    const int nblk = blockIdx.x * 128;

    const uint32_t* Agh = Ah0;
    const uint32_t* Agl = Al0;
    const uint32_t* Bgh = Bh0;
    const uint32_t* Bgl = Bl0;
    if (EPI==0){
        Agh += (size_t)z*S_LEN*DHEAD; Agl += (size_t)z*S_LEN*DHEAD;
        Bgh += (size_t)z*S_LEN*DHEAD; Bgl += (size_t)z*S_LEN*DHEAD;
    }
    if (EPI==1){
        Bgh += (size_t)z*WSZE;
        if (X3) Bgl += (size_t)z*WSZE;
    }
    Agh += (size_t)mblk*lda;  Agl += (size_t)mblk*lda;
    if (BLAY==1){ Bgh += (size_t)nblk*ldb; Bgl += (size_t)nblk*ldb; }
    else        { Bgh += nblk;             Bgl += nblk; }

    float acc[4][4][4];
    #pragma unroll
    for (int i=0;i<4;i++)
        #pragma unroll
        for (int j=0;j<4;j++)
            #pragma unroll
            for (int r=0;r<4;r++) acc[i][j][r]=0.f;

    const int nkt = K >> 5;

    auto issue = [&](int buf){
        uint32_t* Abh = sm + buf*STRIDE;
        uint32_t* Abl = Abh + ASZ;
        uint32_t* Bbh = Abh + NA*ASZ;
        uint32_t* Bbl = Bbh + BSZ;
        #pragma unroll
        for (int i=0;i<4;i++){
            int idx = tid + i*256;
            int off = (idx>>3)*36 + ((idx&7)<<2);
            size_t gsrc = (size_t)(idx>>3)*lda + ((idx&7)<<2);
            cp16(&Abh[off], Agh + gsrc);
            if (X3) cp16(&Abl[off], Agl + gsrc);
        }
        #pragma unroll
        for (int i=0;i<4;i++){
            int idx = tid + i*256;
            if (BLAY==1){
                int off = (idx>>3)*36 + ((idx&7)<<2);
                size_t gsrc = (size_t)(idx>>3)*ldb + ((idx&7)<<2);
                cp16(&Bbh[off], Bgh + gsrc);
                if (X3) cp16(&Bbl[off], Bgl + gsrc);
            } else {
                int off = (idx>>5)*136 + ((idx&31)<<2);
                size_t gsrc = (size_t)(idx>>5)*ldb + ((idx&31)<<2);
                cp16(&Bbh[off], Bgh + gsrc);
                if (X3) cp16(&Bbl[off], Bgl + gsrc);
            }
        }
        asm volatile("cp.async.commit_group;\n" ::: "memory");
    };

    issue(0);

    for (int kt=0; kt<nkt; kt++){
        asm volatile("cp.async.wait_group 0;\n" ::: "memory");
        __syncthreads();
        if (kt+1 < nkt){
            Agh += 32; Agl += 32;
            if (BLAY==1){ Bgh += 32; Bgl += 32; }
            else        { Bgh += (size_t)32*ldb; Bgl += (size_t)32*ldb; }
            issue((kt+1)&1);
        }
        const uint32_t* Ach = sm + (kt&1)*STRIDE;
        const uint32_t* Acl = Ach + ASZ;
        const uint32_t* Bch = Ach + NA*ASZ;
        const uint32_t* Bcl = Bch + BSZ;

        #pragma unroll
        for (int ks=0; ks<4; ks++){
            const int kb = ks*8;
            uint32_t ah[4][4], al[4][4], bh[4][2], bl[4][2];
            #pragma unroll
            for (int mt=0; mt<4; mt++){
                int base = (wm*64 + mt*16 + rl)*36 + kb + cl;
                ah[mt][0]=Ach[base];     ah[mt][1]=Ach[base+288];
                ah[mt][2]=Ach[base+4];   ah[mt][3]=Ach[base+292];
                if (X3){
                    al[mt][0]=Acl[base];     al[mt][1]=Acl[base+288];
                    al[mt][2]=Acl[base+4];   al[mt][3]=Acl[base+292];
                }
            }
            #pragma unroll
            for (int nt=0; nt<4; nt++){
                if (BLAY==1){
                    int base = (wn*32 + nt*8 + rl)*36 + kb + cl;
                    bh[nt][0]=Bch[base]; bh[nt][1]=Bch[base+4];
                    if (X3){ bl[nt][0]=Bcl[base]; bl[nt][1]=Bcl[base+4]; }
                } else {
                    int base = (kb + cl)*136 + wn*32 + nt*8 + rl;
                    bh[nt][0]=Bch[base]; bh[nt][1]=Bch[base+544];
                    if (X3){ bl[nt][0]=Bcl[base]; bl[nt][1]=Bcl[base+544]; }
                }
            }
            #pragma unroll
            for (int mt=0; mt<4; mt++)
                #pragma unroll
                for (int nt=0; nt<4; nt++){
                    mma8(acc[mt][nt], ah[mt], bh[nt]);
                    if (X3){
                        mma8(acc[mt][nt], ah[mt], bl[nt]);
                        mma8(acc[mt][nt], al[mt], bh[nt]);
                    }
                }
        }
    }

    // ---- epilogue ----
    float sg = 1.f, gm = 1.f;
    if (EPI==1 || EPI==3) sg = sig[(EPI==1) ? z : 0];
    if (EPI==3) gm = *gammap;
    const float* bb = (EPI==1 && bias2 && z==1) ? bias2 : bias;
    #pragma unroll
    for (int mt=0; mt<4; mt++){
        #pragma unroll
        for (int nt=0; nt<4; nt++){
            int row0 = mblk + wm*64 + mt*16 + rl;
            int col  = nblk + wn*32 + nt*8 + 2*cl;
            #pragma unroll
            for (int h2=0; h2<2; h2++){
                int row = row0 + h2*8;
                float v0 = acc[mt][nt][h2*2+0];
                float v1 = acc[mt][nt][h2*2+1];
                if (EPI==0){
                    *reinterpret_cast<float2*>(Dst + (size_t)z*S_LEN*S_LEN + (size_t)row*S_LEN + col)
                        = make_float2(v0, v1);
                } else if (EPI==1){
                    float o0 = v0*sg + bb[col];
                    float o1 = v1*sg + bb[col+1];
                    int b = row >> 11, s = row & (S_LEN-1);
                    int h = col >> 7, d = col & (DHEAD-1);
                    size_t o = (size_t)z*QSZ + (((size_t)(b*NHEAD+h))*S_LEN + s)*DHEAD + d;
                    uint32_t h0 = f2tf(o0), h1 = f2tf(o1);
                    *reinterpret_cast<uint2*>(Dh + o) = make_uint2(h0, h1);
                    if (X3){
                        *reinterpret_cast<uint2*>(Dl + o) =
                            make_uint2(f2tf(o0-__uint_as_float(h0)), f2tf(o1-__uint_as_float(h1)));
                    }
                } else {
                    size_t idx = (size_t)row*FDIM + col;
                    float o0 = x0[idx]   + (v0*sg + bb[col])*gm;
                    float o1 = x0[idx+1] + (v1*sg + bb[col+1])*gm;
                    *reinterpret_cast<float2*>(Dst + idx) = make_float2(o0, o1);
                }
            }
        }
    }

    // ---- QK softmax stats ----
    if constexpr (EPI==0){
        __shared__ float sMx[4][128];
        __shared__ float sSm[4][128];
        #pragma unroll
        for (int mt=0; mt<4; mt++){
            #pragma unroll
            for (int h2=0; h2<2; h2++){
                float m = acc[mt][0][h2*2];
                #pragma unroll
                for (int nt=0; nt<4; nt++){
                    m = fmaxf(m, acc[mt][nt][h2*2+0]);
                    m = fmaxf(m, acc[mt][nt][h2*2+1]);
                }
                float s = 0.f;
                #pragma unroll
                for (int nt=0; nt<4; nt++){
                    s += __expf(acc[mt][nt][h2*2+0] - m);
                    s += __expf(acc[mt][nt][h2*2+1] - m);
                }
                #pragma unroll
                for (int off=1; off<4; off<<=1){
                    float om = __shfl_xor_sync(0xffffffffu, m, off);
                    float os = __shfl_xor_sync(0xffffffffu, s, off);
                    float nm = fmaxf(m, om);
                    s = s*__expf(m-nm) + os*__expf(om-nm);
                    m = nm;
                }
                if (cl==0){
                    int rloc = wm*64 + mt*16 + h2*8 + rl;
                    sMx[wn][rloc] = m;
                    sSm[wn][rloc] = s;
                }
            }
        }
        __syncthreads();
        if (tid < 128){
            float M = sMx[0][tid], S = sSm[0][tid];
            #pragma unroll
            for (int w=1; w<4; w++){
                float m2 = sMx[w][tid], s2 = sSm[w][tid];
                float nm = fmaxf(M, m2);
                S = S*__expf(M-nm) + s2*__expf(m2-nm);
                M = nm;
            }
            g_stats[((size_t)z*S_LEN + mblk + tid)*16 + blockIdx.x] = make_float2(M, S);
        }
    }
}

// ---------------- merge per-block stats -> per-row (M, 1/Z) ----------------
__global__ void k_merge(){
    size_t r = (size_t)blockIdx.x*256 + threadIdx.x;
    const float2* st = g_stats + r*16;
    float2 p0 = st[0];
    float M = p0.x, S = p0.y;
    #pragma unroll
    for (int i=1;i<16;i++){
        float2 p = st[i];
        float nm = fmaxf(M, p.x);
        S = S*__expf(M-nm) + p.y*__expf(p.x-nm);
        M = nm;
    }
    g_rowM[r] = M;
    g_rowI[r] = 1.f/S;
}

// ---------------- AV GEMM: pipelined, fused softmax-normalize + writeback ---
// attn: raw logits in, probs out (in place). B = v (tf32). Dst = ctx (tf32).
// Pipeline: cp.async 3-buffered B, 2-buffered tf32-A smem, 2-deep LDG->exp->STS.
// One __syncthreads per k-tile.
__global__ void __launch_bounds__(256,2) gemm_av(
    float* __restrict__ attn,
    const uint32_t* __restrict__ Bv,
    uint32_t* __restrict__ Dst)
{
    extern __shared__ uint32_t avsm[];
    uint32_t* Atf = avsm;            // 2 x 128*36
    uint32_t* Btf = avsm + 2*4608;   // 3 x 32*136
    __shared__ float sM[128], sI[128];

    const int tid = threadIdx.x;
    const int lane = tid & 31;
    const int warp = tid >> 5;
    const int wm = warp >> 2;
    const int wn = warp & 3;
    const int rl = lane >> 2;
    const int cl = lane & 3;
    const int z = blockIdx.z;
    const int mblk = blockIdx.y * 128;
    const int nkt = S_LEN >> 5;      // 64

    if (tid < 128){
        sM[tid] = g_rowM[(size_t)z*S_LEN + mblk + tid];
        sI[tid] = g_rowI[(size_t)z*S_LEN + mblk + tid];
    }

    float*          Ag = attn + (size_t)z*S_LEN*S_LEN + (size_t)mblk*S_LEN;
    const uint32_t* Bg = Bv   + (size_t)z*S_LEN*DHEAD;

    // per-thread chunk geometry (same chunks for LDG, transform, STS, STG)
    int crow[4], ckk[4];
    #pragma unroll
    for (int i=0;i<4;i++){ int idx = tid + i*256; crow[i]=idx>>3; ckk[i]=(idx&7)<<2; }

    auto issueB = [&](int t){
        int bb = t % 3;
        #pragma unroll
        for (int i=0;i<4;i++){
            int idx = tid + i*256;
            cp16(&Btf[bb*4352 + (idx>>5)*136 + ((idx&31)<<2)],
                 Bg + ((size_t)t*32 + (idx>>5))*DHEAD + ((idx&31)<<2));
        }
        asm volatile("cp.async.commit_group;\n" ::: "memory");
    };

    float4 ra[2][4];
    auto ldgA = [&](int t){
        #pragma unroll
        for (int i=0;i<4;i++)
            ra[t&1][i] = *reinterpret_cast<const float4*>(Ag + (size_t)crow[i]*S_LEN + t*32 + ckk[i]);
    };
    auto xform = [&](int t){
        int ab = t & 1;
        #pragma unroll
        for (int i=0;i<4;i++){
            float M = sM[crow[i]], inv = sI[crow[i]];
            float4 v = ra[ab][i];
            float4 p;
            p.x = __expf(v.x - M)*inv;
            p.y = __expf(v.y - M)*inv;
            p.z = __expf(v.z - M)*inv;
            p.w = __expf(v.w - M)*inv;
            *reinterpret_cast<uint4*>(&Atf[ab*4608 + crow[i]*36 + ckk[i]]) =
                make_uint4(f2tf(p.x), f2tf(p.y), f2tf(p.z), f2tf(p.w));
            *reinterpret_cast<float4*>(Ag + (size_t)crow[i]*S_LEN + t*32 + ckk[i]) = p;
        }
    };

    float acc[4][4][4];
    #pragma unroll
    for (int i=0;i<4;i++)
        #pragma unroll
        for (int j=0;j<4;j++)
            #pragma unroll
            for (int r=0;r<4;r++) acc[i][j][r]=0.f;

    // prologue
    issueB(0);
    ldgA(0);
    issueB(1);
    ldgA(1);
    __syncthreads();          // sM/sI visible
    xform(0);                 // STS Atf[0] + STG probs tile 0

    for (int kt=0; kt<nkt; kt++){
        asm volatile("cp.async.wait_group 0;\n" ::: "memory");
        __syncthreads();      // publish Atf[kt&1], Btf[kt%3]; prev compute done
        if (kt+2 < nkt){
            issueB(kt+2);
            ldgA(kt+2);
        }
        if (kt+1 < nkt) xform(kt+1);

        const uint32_t* Ah = Atf + (kt&1)*4608;
        const uint32_t* Bh = Btf + (kt%3)*4352;
        #pragma unroll
        for (int ks=0; ks<4; ks++){
            const int kb = ks*8;
            uint32_t ah[4][4], bh[4][2];
            #pragma unroll
            for (int mt=0; mt<4; mt++){
                int base = (wm*64 + mt*16 + rl)*36 + kb + cl;
                ah[mt][0]=Ah[base];     ah[mt][1]=Ah[base+288];
                ah[mt][2]=Ah[base+4];   ah[mt][3]=Ah[base+292];
            }
            #pragma unroll
            for (int nt=0; nt<4; nt++){
                int base = (kb + cl)*136 + wn*32 + nt*8 + rl;
                bh[nt][0]=Bh[base]; bh[nt][1]=Bh[base+544];
            }
            #pragma unroll
            for (int mt=0; mt<4; mt++)
                #pragma unroll
                for (int nt=0; nt<4; nt++)
                    mma8(acc[mt][nt], ah[mt], bh[nt]);
        }
    }

    const int b = z >> 3, h = z & 7;
    #pragma unroll
    for (int mt=0; mt<4; mt++){
        #pragma unroll
        for (int nt=0; nt<4; nt++){
            int row0 = mblk + wm*64 + mt*16 + rl;
            int col  = wn*32 + nt*8 + 2*cl;
            #pragma unroll
            for (int h2=0; h2<2; h2++){
                int row = row0 + h2*8;
                *reinterpret_cast<uint2*>(Dst + ((size_t)b*S_LEN + row)*FDIM + h*DHEAD + col)
                    = make_uint2(f2tf(acc[mt][nt][h2*2+0]), f2tf(acc[mt][nt][h2*2+1]));
            }
        }
    }
}

// ---------------- launch ----------------
extern "C" void kernel_launch(void* const* d_in, const int* in_sizes, int n_in,
                              void* d_out, int out_size)
{
    (void)in_sizes; (void)n_in; (void)out_size;
    const float* x  = (const float*)d_in[0];
    const float* wq = (const float*)d_in[1];
    const float* bq = (const float*)d_in[2];
    const float* uq = (const float*)d_in[3];
    const float* wk = (const float*)d_in[4];
    const float* bk = (const float*)d_in[5];
    const float* uk = (const float*)d_in[6];
    const float* wv = (const float*)d_in[7];
    const float* bv = (const float*)d_in[8];
    const float* uv = (const float*)d_in[9];
    const float* wo = (const float*)d_in[10];
    const float* bo = (const float*)d_in[11];
    const float* uo = (const float*)d_in[12];
    const float* gm = (const float*)d_in[13];

    float* out  = (float*)d_out;
    float* attn = out + (size_t)NTOK*FDIM;

    uint32_t *pxh,*pxl,*pwh,*pwl,*pqkh,*pqkl,*pvh,*pctxh;
    float *psig;
    cudaGetSymbolAddress((void**)&pxh,  g_xh);
    cudaGetSymbolAddress((void**)&pxl,  g_xl);
    cudaGetSymbolAddress((void**)&pwh,  g_wh);
    cudaGetSymbolAddress((void**)&pwl,  g_wl);
    cudaGetSymbolAddress((void**)&pqkh, g_qkh);
    cudaGetSymbolAddress((void**)&pqkl, g_qkl);
    cudaGetSymbolAddress((void**)&pvh,  g_vh);
    cudaGetSymbolAddress((void**)&pctxh,g_ctxh);
    cudaGetSymbolAddress((void**)&psig, g_sig);

    cudaFuncSetAttribute(gemm_pre<1,true ,1>, cudaFuncAttributeMaxDynamicSharedMemorySize, 143360);
    cudaFuncSetAttribute(gemm_pre<1,false,2>, cudaFuncAttributeMaxDynamicSharedMemorySize, 71680);
    cudaFuncSetAttribute(gemm_pre<3,false,2>, cudaFuncAttributeMaxDynamicSharedMemorySize, 71680);
    cudaFuncSetAttribute(gemm_pre<0,true ,1>, cudaFuncAttributeMaxDynamicSharedMemorySize, 147456);
    cudaFuncSetAttribute(gemm_av,             cudaFuncAttributeMaxDynamicSharedMemorySize, 89088);

    // operand pre-splits (merged) + spectral norms (exact fp32)
    k_split_all<<<8192+4*1024,256>>>((const float4*)x,(const float4*)wq,(const float4*)wk,
                                     (const float4*)wv,(const float4*)wo,
                                     (uint4*)pxh,(uint4*)pxl,(uint4*)pwh,(uint4*)pwl);
    k_sigma_v<<<dim3(128,4),256>>>(wq,wk,wv,wo, uq,uk,uv,uo);
    k_sigma_s<<<dim3(4,4),256>>>(wq,wk,wv,wo);
    k_sigma_fin<<<4,256>>>();

    // merged q+k projection (x3, z=2), v projection (x1, 2 CTAs/SM)
    gemm_pre<1,true ,1><<<dim3(8,64,2),256,143360>>>(pxh,pxl, pwh,pwl,
        nullptr, pqkh, pqkl, FDIM, FDIM, FDIM, psig, bq, bk, nullptr, nullptr);
    gemm_pre<1,false,2><<<dim3(8,64,1),256,71680>>>(pxh,nullptr, pwh+2*WSZE,nullptr,
        nullptr, pvh, nullptr, FDIM, FDIM, FDIM, psig+2, bv, nullptr, nullptr, nullptr);

    // logits = q k^T (x3) + stats
    gemm_pre<0,true ,1><<<dim3(16,16,32),256,147456>>>(pqkh,pqkl, pqkh+QSZ,pqkl+QSZ,
        attn, nullptr, nullptr, DHEAD, DHEAD, DHEAD, nullptr, nullptr, nullptr, nullptr, nullptr);
    k_merge<<<(ZTOT*S_LEN)/256,256>>>();

    // ctx = softmax(logits) @ v (x1, pipelined), probs in place, ctx tf32
    gemm_av<<<dim3(1,16,32),256,89088>>>(attn, pvh, pctxh);

    // out = x + (ctx @ wo + bo) * gamma (x1, 2 CTAs/SM)
    gemm_pre<3,false,2><<<dim3(8,64,1),256,71680>>>(pctxh,nullptr, pwh+3*WSZE,nullptr,
        out, nullptr, nullptr, FDIM, FDIM, FDIM, psig+3, bo, nullptr, x, gm);
}

// round 9
// speedup vs baseline: 1.7011x; 1.3983x over previous
#include <cuda_runtime.h>
#include <cuda_bf16.h>
#include <cstdint>

#define BATCH 4
#define NHEAD 8
#define S_LEN 2048
#define FDIM  1024
#define DHEAD 128
#define ZTOT  (BATCH*NHEAD)
#define NTOK  (BATCH*S_LEN)
#define QSZ   ((size_t)ZTOT*S_LEN*DHEAD)
#define WSZE  ((size_t)FDIM*FDIM)

// ---------------- scratch ----------------
static __device__ float g_sig[4];
static __device__ float g_v1[4][FDIM];
static __device__ float g_s1[4][FDIM];
static __device__ __align__(128) uint32_t g_xtf[(size_t)NTOK*FDIM];     // x tf32 (v proj)
static __device__ __align__(128) uint16_t g_xbh[(size_t)NTOK*FDIM];     // x bf16 hi
static __device__ __align__(128) uint16_t g_xbl[(size_t)NTOK*FDIM];     // x bf16 lo
static __device__ __align__(128) uint32_t g_wtf[2][WSZE];               // wv, wo tf32 (n-contig)
static __device__ __align__(128) uint16_t g_wth[2*WSZE];                // wq^T, wk^T bf16 hi [out][in]
static __device__ __align__(128) uint16_t g_wtl[2*WSZE];                // wq^T, wk^T bf16 lo
static __device__ __align__(128) uint16_t g_qkh[2*QSZ];                 // q,k bf16 hi [B,H,S,D]
static __device__ __align__(128) uint16_t g_qkl[2*QSZ];                 // q,k bf16 lo
static __device__ __align__(128) uint32_t g_vh[QSZ];                    // v tf32
static __device__ __align__(128) uint32_t g_ctxh[(size_t)NTOK*FDIM];    // ctx tf32
static __device__ __align__(128) float2 g_stats[(size_t)ZTOT*S_LEN*16];
static __device__ float g_rowM[(size_t)ZTOT*S_LEN];
static __device__ float g_rowI[(size_t)ZTOT*S_LEN];

// ---------------- helpers ----------------
__device__ __forceinline__ float warp_sum(float v){
    #pragma unroll
    for (int o=16;o;o>>=1) v += __shfl_xor_sync(0xffffffffu, v, o);
    return v;
}
__device__ __forceinline__ uint32_t f2tf(float x){
    uint32_t r; asm("cvt.rna.tf32.f32 %0, %1;" : "=r"(r) : "f"(x)); return r;
}
__device__ __forceinline__ uint16_t f2bf(float x){
    __nv_bfloat16 h = __float2bfloat16(x);
    return *reinterpret_cast<uint16_t*>(&h);
}
__device__ __forceinline__ float bf2f(uint16_t u){
    __nv_bfloat16 h; *reinterpret_cast<uint16_t*>(&h) = u;
    return __bfloat162float(h);
}
__device__ __forceinline__ void mma8(float* c, const uint32_t* a, const uint32_t* b){
    asm volatile(
        "mma.sync.aligned.m16n8k8.row.col.f32.tf32.tf32.f32 "
        "{%0,%1,%2,%3},{%4,%5,%6,%7},{%8,%9},{%0,%1,%2,%3};\n"
        : "+f"(c[0]), "+f"(c[1]), "+f"(c[2]), "+f"(c[3])
        : "r"(a[0]), "r"(a[1]), "r"(a[2]), "r"(a[3]), "r"(b[0]), "r"(b[1]));
}
__device__ __forceinline__ void mma16(float* c, const uint32_t* a, const uint32_t* b){
    asm volatile(
        "mma.sync.aligned.m16n8k16.row.col.f32.bf16.bf16.f32 "
        "{%0,%1,%2,%3},{%4,%5,%6,%7},{%8,%9},{%0,%1,%2,%3};\n"
        : "+f"(c[0]), "+f"(c[1]), "+f"(c[2]), "+f"(c[3])
        : "r"(a[0]), "r"(a[1]), "r"(a[2]), "r"(a[3]), "r"(b[0]), "r"(b[1]));
}
__device__ __forceinline__ void cp16(void* s, const void* g){
    uint32_t sa = (uint32_t)__cvta_generic_to_shared(s);
    asm volatile("cp.async.cg.shared.global [%0], [%1], 16;\n" :: "r"(sa), "l"(g));
}

// ---------------- conversions ----------------
// x -> tf32 + bf16 hi/lo
__global__ void __launch_bounds__(256) k_conv_x(const float4* __restrict__ x,
    uint4* __restrict__ xtf, uint2* __restrict__ xbh, uint2* __restrict__ xbl){
    size_t i = (size_t)blockIdx.x*256 + threadIdx.x;
    float4 v = x[i];
    xtf[i] = make_uint4(f2tf(v.x), f2tf(v.y), f2tf(v.z), f2tf(v.w));
    uint16_t h0=f2bf(v.x), h1=f2bf(v.y), h2=f2bf(v.z), h3=f2bf(v.w);
    xbh[i] = make_uint2((uint32_t)h0 | ((uint32_t)h1<<16), (uint32_t)h2 | ((uint32_t)h3<<16));
    uint16_t l0=f2bf(v.x-bf2f(h0)), l1=f2bf(v.y-bf2f(h1)),
             l2=f2bf(v.z-bf2f(h2)), l3=f2bf(v.w-bf2f(h3));
    xbl[i] = make_uint2((uint32_t)l0 | ((uint32_t)l1<<16), (uint32_t)l2 | ((uint32_t)l3<<16));
}
// wv, wo -> tf32 (n-contig, layout unchanged)
__global__ void __launch_bounds__(256) k_conv_w(const float4* __restrict__ wv,
    const float4* __restrict__ wo, uint4* __restrict__ wtf){
    const int NWB = (int)(WSZE/4)/256;  // 1024
    int b = blockIdx.x;
    const float4* src = (b < NWB) ? wv : wo;
    size_t i = (size_t)(b % NWB)*256 + threadIdx.x;
    float4 v = src[i];
    wtf[(b<NWB?0:1)*(WSZE/4) + i] = make_uint4(f2tf(v.x), f2tf(v.y), f2tf(v.z), f2tf(v.w));
}
// wq, wk -> transposed bf16 hi/lo: Wt[n][k] = W[k][n]
__global__ void __launch_bounds__(256) k_transp(const float* __restrict__ w0,
    const float* __restrict__ w1, uint16_t* __restrict__ th, uint16_t* __restrict__ tl){
    __shared__ float t[32][33];
    int s = blockIdx.z;
    const float* W = s ? w1 : w0;
    uint16_t* Th = th + (size_t)s*WSZE;
    uint16_t* Tl = tl + (size_t)s*WSZE;
    int k0 = blockIdx.y*32, n0 = blockIdx.x*32;
    int r = threadIdx.x>>5, c = threadIdx.x&31;
    #pragma unroll
    for (int i=0;i<4;i++)
        t[r+8*i][c] = W[(size_t)(k0+r+8*i)*FDIM + n0 + c];
    __syncthreads();
    #pragma unroll
    for (int i=0;i<4;i++){
        float v = t[c][r+8*i];
        uint16_t hi = f2bf(v);
        size_t o = (size_t)(n0+r+8*i)*FDIM + k0 + c;
        Th[o] = hi;
        Tl[o] = f2bf(v - bf2f(hi));
    }
}

// ---------------- spectral norm (exact fp32) ----------------
__global__ void k_sigma_v(const float* w0,const float* w1,const float* w2,const float* w3,
                          const float* u0,const float* u1,const float* u2,const float* u3){
    const float* Wt[4]={w0,w1,w2,w3};
    const float* Ut[4]={u0,u1,u2,u3};
    int wi = blockIdx.y;
    const float* W = Wt[wi];
    const float* U = Ut[wi];
    int lane = threadIdx.x&31, warp = threadIdx.x>>5;
    int row = blockIdx.x*8 + warp;
    const float* r = W + (size_t)row*FDIM;
    float acc = 0.f;
    for (int j=lane;j<FDIM;j+=32) acc += U[j]*r[j];
    acc = warp_sum(acc);
    if (!lane) g_v1[wi][row] = acc;
}
__global__ void k_sigma_s(const float* w0,const float* w1,const float* w2,const float* w3){
    const float* Wt[4]={w0,w1,w2,w3};
    int wi = blockIdx.y;
    const float* W = Wt[wi];
    int o = blockIdx.x*256 + threadIdx.x;
    float acc = 0.f;
    for (int i=0;i<FDIM;i++) acc += g_v1[wi][i]*W[(size_t)i*FDIM+o];
    g_s1[wi][o] = acc;
}
__global__ void k_sigma_fin(){
    __shared__ float rv[8], rs[8];
    int wi = blockIdx.x, tid = threadIdx.x;
    float sv=0.f, ss=0.f;
    for (int i=tid;i<FDIM;i+=256){
        float a=g_v1[wi][i]; sv += a*a;
        float b=g_s1[wi][i]; ss += b*b;
    }
    sv = warp_sum(sv); ss = warp_sum(ss);
    if ((tid&31)==0){ rv[tid>>5]=sv; rs[tid>>5]=ss; }
    __syncthreads();
    if (tid==0){
        float a=0.f,b=0.f;
        for (int i=0;i<8;i++){ a+=rv[i]; b+=rs[i]; }
        g_sig[wi] = sqrtf(a/b);
    }
}

// ---------------- bf16x3 GEMM (fp32-class), BLAY=1 (C = A B^T, k-contig) ----
// CTA 128x128, k-tile 32 (= 16 u32 words/row, stride 20), 8 warps (2x4).
// EPI==0: QK logits -> Dst + z*S*S, + softmax stats. A,B offset by z*S*D.
// EPI==1: proj q/k: z selects weight/bias/sig; out = (acc*sig + bias) split
//         to bf16 hi/lo, head-split write at Dhi/Dlo + z*QSZ.
template<int EPI>
__global__ void __launch_bounds__(256,2) gemm_bf3(
    const uint16_t* __restrict__ Ah0, const uint16_t* __restrict__ Al0,
    const uint16_t* __restrict__ Bh0, const uint16_t* __restrict__ Bl0,
    float* __restrict__ Dst, uint16_t* __restrict__ Dhi, uint16_t* __restrict__ Dlo,
    int K, int lda, int ldb,
    const float* __restrict__ sig, const float* __restrict__ b0p,
    const float* __restrict__ b1p)
{
    constexpr int RW  = 20;         // u32 words per 32-elem row (16 + 4 pad)
    constexpr int ARR = 128*RW;     // words per array
    constexpr int STRIDE = 4*ARR;   // Ahi,Alo,Bhi,Blo
    extern __shared__ uint32_t sm[];

    const int tid = threadIdx.x;
    const int lane = tid & 31;
    const int warp = tid >> 5;
    const int wm = warp >> 2;
    const int wn = warp & 3;
    const int rl = lane >> 2;
    const int cl = lane & 3;
    const int z = blockIdx.z;
    const int mblk = blockIdx.y * 128;
    const int nblk = blockIdx.x * 128;

    const uint16_t* Agh = Ah0;
    const uint16_t* Agl = Al0;
    const uint16_t* Bgh = Bh0;
    const uint16_t* Bgl = Bl0;
    if (EPI==0){
        size_t zo = (size_t)z*S_LEN*DHEAD;
        Agh += zo; Agl += zo; Bgh += zo; Bgl += zo;
    } else {
        Bgh += (size_t)z*WSZE; Bgl += (size_t)z*WSZE;
    }
    Agh += (size_t)mblk*lda; Agl += (size_t)mblk*lda;
    Bgh += (size_t)nblk*ldb; Bgl += (size_t)nblk*ldb;

    float acc[4][4][4];
    #pragma unroll
    for (int i=0;i<4;i++)
        #pragma unroll
        for (int j=0;j<4;j++)
            #pragma unroll
            for (int r=0;r<4;r++) acc[i][j][r]=0.f;

    const int nkt = K >> 5;

    auto issue = [&](int buf){
        uint32_t* Ah = sm + buf*STRIDE;
        uint32_t* Al = Ah + ARR;
        uint32_t* Bh = Ah + 2*ARR;
        uint32_t* Bl = Ah + 3*ARR;
        #pragma unroll
        for (int i=0;i<2;i++){
            int idx = tid + i*256;
            int row = idx>>2, ch = idx&3;
            int off = row*RW + ch*4;
            size_t ga = (size_t)row*lda + ch*8;
            size_t gb = (size_t)row*ldb + ch*8;
            cp16(&Ah[off], Agh + ga);
            cp16(&Al[off], Agl + ga);
            cp16(&Bh[off], Bgh + gb);
            cp16(&Bl[off], Bgl + gb);
        }
        asm volatile("cp.async.commit_group;\n" ::: "memory");
    };

    issue(0);

    for (int kt=0; kt<nkt; kt++){
        asm volatile("cp.async.wait_group 0;\n" ::: "memory");
        __syncthreads();
        if (kt+1 < nkt){
            Agh += 32; Agl += 32; Bgh += 32; Bgl += 32;
            issue((kt+1)&1);
        }
        const uint32_t* Ah = sm + (kt&1)*STRIDE;
        const uint32_t* Al = Ah + ARR;
        const uint32_t* Bh = Ah + 2*ARR;
        const uint32_t* Bl = Ah + 3*ARR;

        #pragma unroll
        for (int ks=0; ks<2; ks++){
            const int kb = ks*8;
            uint32_t ah[4][4], al[4][4];
            #pragma unroll
            for (int mt=0; mt<4; mt++){
                int base = (wm*64 + mt*16 + rl)*RW + kb + cl;
                ah[mt][0]=Ah[base];       ah[mt][1]=Ah[base+8*RW];
                ah[mt][2]=Ah[base+4];     ah[mt][3]=Ah[base+8*RW+4];
                al[mt][0]=Al[base];       al[mt][1]=Al[base+8*RW];
                al[mt][2]=Al[base+4];     al[mt][3]=Al[base+8*RW+4];
            }
            #pragma unroll
            for (int nt=0; nt<4; nt++){
                int bb = (wn*32 + nt*8 + rl)*RW + kb + cl;
                uint32_t bh[2], bl[2];
                bh[0]=Bh[bb]; bh[1]=Bh[bb+4];
                bl[0]=Bl[bb]; bl[1]=Bl[bb+4];
                #pragma unroll
                for (int mt=0; mt<4; mt++){
                    mma16(acc[mt][nt], ah[mt], bh);
                    mma16(acc[mt][nt], ah[mt], bl);
                    mma16(acc[mt][nt], al[mt], bh);
                }
            }
        }
    }

    // ---- epilogue ----
    float sg = 1.f;
    if (EPI==1) sg = sig[z];
    const float* bb = (EPI==1) ? (z ? b1p : b0p) : b0p;
    #pragma unroll
    for (int mt=0; mt<4; mt++){
        #pragma unroll
        for (int nt=0; nt<4; nt++){
            int row0 = mblk + wm*64 + mt*16 + rl;
            int col  = nblk + wn*32 + nt*8 + 2*cl;
            #pragma unroll
            for (int h2=0; h2<2; h2++){
                int row = row0 + h2*8;
                float v0 = acc[mt][nt][h2*2+0];
                float v1 = acc[mt][nt][h2*2+1];
                if (EPI==0){
                    *reinterpret_cast<float2*>(Dst + (size_t)z*S_LEN*S_LEN + (size_t)row*S_LEN + col)
                        = make_float2(v0, v1);
                } else {
                    float o0 = v0*sg + bb[col];
                    float o1 = v1*sg + bb[col+1];
                    int b = row >> 11, s = row & (S_LEN-1);
                    int h = col >> 7, d = col & (DHEAD-1);
                    size_t o = (size_t)z*QSZ + (((size_t)(b*NHEAD+h))*S_LEN + s)*DHEAD + d;
                    uint16_t h0 = f2bf(o0), h1 = f2bf(o1);
                    *reinterpret_cast<uint32_t*>(Dhi + o) = (uint32_t)h0 | ((uint32_t)h1<<16);
                    uint16_t l0 = f2bf(o0 - bf2f(h0)), l1 = f2bf(o1 - bf2f(h1));
                    *reinterpret_cast<uint32_t*>(Dlo + o) = (uint32_t)l0 | ((uint32_t)l1<<16);
                }
            }
        }
    }

    if constexpr (EPI==0){
        __shared__ float sMx[4][128];
        __shared__ float sSm[4][128];
        #pragma unroll
        for (int mt=0; mt<4; mt++){
            #pragma unroll
            for (int h2=0; h2<2; h2++){
                float m = acc[mt][0][h2*2];
                #pragma unroll
                for (int nt=0; nt<4; nt++){
                    m = fmaxf(m, acc[mt][nt][h2*2+0]);
                    m = fmaxf(m, acc[mt][nt][h2*2+1]);
                }
                float s = 0.f;
                #pragma unroll
                for (int nt=0; nt<4; nt++){
                    s += __expf(acc[mt][nt][h2*2+0] - m);
                    s += __expf(acc[mt][nt][h2*2+1] - m);
                }
                #pragma unroll
                for (int off=1; off<4; off<<=1){
                    float om = __shfl_xor_sync(0xffffffffu, m, off);
                    float os = __shfl_xor_sync(0xffffffffu, s, off);
                    float nm = fmaxf(m, om);
                    s = s*__expf(m-nm) + os*__expf(om-nm);
                    m = nm;
                }
                if (cl==0){
                    int rloc = wm*64 + mt*16 + h2*8 + rl;
                    sMx[wn][rloc] = m;
                    sSm[wn][rloc] = s;
                }
            }
        }
        __syncthreads();
        if (tid < 128){
            float M = sMx[0][tid], S = sSm[0][tid];
            #pragma unroll
            for (int w=1; w<4; w++){
                float m2 = sMx[w][tid], s2 = sSm[w][tid];
                float nm = fmaxf(M, m2);
                S = S*__expf(M-nm) + s2*__expf(m2-nm);
                M = nm;
            }
            g_stats[((size_t)z*S_LEN + mblk + tid)*16 + blockIdx.x] = make_float2(M, S);
        }
    }
}

// ---------------- tf32 x1 GEMM (v proj / out proj), BLAY=0 ----------
template<int EPI>
__global__ void __launch_bounds__(256,2) gemm_tf(
    const uint32_t* __restrict__ A0, const uint32_t* __restrict__ B0,
    float* __restrict__ Dst, uint32_t* __restrict__ Dh,
    int K, int lda, int ldb,
    const float* __restrict__ sig, const float* __restrict__ b0p,
    const float* __restrict__ x0, const float* __restrict__ gammap)
{
    constexpr int ASZ = 128*36;
    constexpr int BSZ = 32*136;
    constexpr int STRIDE = ASZ + BSZ;
    extern __shared__ uint32_t sm[];

    const int tid = threadIdx.x;
    const int lane = tid & 31;
    const int warp = tid >> 5;
    const int wm = warp >> 2;
    const int wn = warp & 3;
    const int rl = lane >> 2;
    const int cl = lane & 3;
    const int mblk = blockIdx.y * 128;
    const int nblk = blockIdx.x * 128;

    const uint32_t* Ag = A0 + (size_t)mblk*lda;
    const uint32_t* Bg = B0 + nblk;

    float acc[4][4][4];
    #pragma unroll
    for (int i=0;i<4;i++)
        #pragma unroll
        for (int j=0;j<4;j++)
            #pragma unroll
            for (int r=0;r<4;r++) acc[i][j][r]=0.f;

    const int nkt = K >> 5;

    auto issue = [&](int buf){
        uint32_t* Ab = sm + buf*STRIDE;
        uint32_t* Bb = Ab + ASZ;
        #pragma unroll
        for (int i=0;i<4;i++){
            int idx = tid + i*256;
            cp16(&Ab[(idx>>3)*36 + ((idx&7)<<2)], Ag + (size_t)(idx>>3)*lda + ((idx&7)<<2));
        }
        #pragma unroll
        for (int i=0;i<4;i++){
            int idx = tid + i*256;
            cp16(&Bb[(idx>>5)*136 + ((idx&31)<<2)], Bg + (size_t)(idx>>5)*ldb + ((idx&31)<<2));
        }
        asm volatile("cp.async.commit_group;\n" ::: "memory");
    };

    issue(0);

    for (int kt=0; kt<nkt; kt++){
        asm volatile("cp.async.wait_group 0;\n" ::: "memory");
        __syncthreads();
        if (kt+1 < nkt){
            Ag += 32;
            Bg += (size_t)32*ldb;
            issue((kt+1)&1);
        }
        const uint32_t* Ac = sm + (kt&1)*STRIDE;
        const uint32_t* Bc = Ac + ASZ;

        #pragma unroll
        for (int ks=0; ks<4; ks++){
            const int kb = ks*8;
            uint32_t ah[4][4], bh[4][2];
            #pragma unroll
            for (int mt=0; mt<4; mt++){
                int base = (wm*64 + mt*16 + rl)*36 + kb + cl;
                ah[mt][0]=Ac[base];     ah[mt][1]=Ac[base+288];
                ah[mt][2]=Ac[base+4];   ah[mt][3]=Ac[base+292];
            }
            #pragma unroll
            for (int nt=0; nt<4; nt++){
                int base = (kb + cl)*136 + wn*32 + nt*8 + rl;
                bh[nt][0]=Bc[base]; bh[nt][1]=Bc[base+544];
            }
            #pragma unroll
            for (int mt=0; mt<4; mt++)
                #pragma unroll
                for (int nt=0; nt<4; nt++)
                    mma8(acc[mt][nt], ah[mt], bh[nt]);
        }
    }

    float sg = (EPI==1) ? sig[0] : sig[3];
    float gm = (EPI==3) ? *gammap : 1.f;
    #pragma unroll
    for (int mt=0; mt<4; mt++){
        #pragma unroll
        for (int nt=0; nt<4; nt++){
            int row0 = mblk + wm*64 + mt*16 + rl;
            int col  = nblk + wn*32 + nt*8 + 2*cl;
            #pragma unroll
            for (int h2=0; h2<2; h2++){
                int row = row0 + h2*8;
                float v0 = acc[mt][nt][h2*2+0];
                float v1 = acc[mt][nt][h2*2+1];
                if (EPI==1){
                    float o0 = v0*sg + b0p[col];
                    float o1 = v1*sg + b0p[col+1];
                    int b = row >> 11, s = row & (S_LEN-1);
                    int h = col >> 7, d = col & (DHEAD-1);
                    size_t o = (((size_t)(b*NHEAD+h))*S_LEN + s)*DHEAD + d;
                    *reinterpret_cast<uint2*>(Dh + o) = make_uint2(f2tf(o0), f2tf(o1));
                } else {
                    size_t idx = (size_t)row*FDIM + col;
                    float o0 = x0[idx]   + (v0*sg + b0p[col])*gm;
                    float o1 = x0[idx+1] + (v1*sg + b0p[col+1])*gm;
                    *reinterpret_cast<float2*>(Dst + idx) = make_float2(o0, o1);
                }
            }
        }
    }
}

// ---------------- merge stats ----------------
__global__ void k_merge(){
    size_t r = (size_t)blockIdx.x*256 + threadIdx.x;
    const float2* st = g_stats + r*16;
    float2 p0 = st[0];
    float M = p0.x, S = p0.y;
    #pragma unroll
    for (int i=1;i<16;i++){
        float2 p = st[i];
        float nm = fmaxf(M, p.x);
        S = S*__expf(M-nm) + p.y*__expf(p.x-nm);
        M = nm;
    }
    g_rowM[r] = M;
    g_rowI[r] = 1.f/S;
}

// ---------------- AV GEMM: pipelined softmax-normalize + writeback ----------
__global__ void __launch_bounds__(256,2) gemm_av(
    float* __restrict__ attn,
    const uint32_t* __restrict__ Bv,
    uint32_t* __restrict__ Dst)
{
    extern __shared__ uint32_t avsm[];
    uint32_t* Atf = avsm;            // 2 x 128*36
    uint32_t* Btf = avsm + 2*4608;   // 3 x 32*136
    __shared__ float sM[128], sI[128];

    const int tid = threadIdx.x;
    const int lane = tid & 31;
    const int warp = tid >> 5;
    const int wm = warp >> 2;
    const int wn = warp & 3;
    const int rl = lane >> 2;
    const int cl = lane & 3;
    const int z = blockIdx.z;
    const int mblk = blockIdx.y * 128;
    const int nkt = S_LEN >> 5;

    if (tid < 128){
        sM[tid] = g_rowM[(size_t)z*S_LEN + mblk + tid];
        sI[tid] = g_rowI[(size_t)z*S_LEN + mblk + tid];
    }

    float*          Ag = attn + (size_t)z*S_LEN*S_LEN + (size_t)mblk*S_LEN;
    const uint32_t* Bg = Bv   + (size_t)z*S_LEN*DHEAD;

    int crow[4], ckk[4];
    #pragma unroll
    for (int i=0;i<4;i++){ int idx = tid + i*256; crow[i]=idx>>3; ckk[i]=(idx&7)<<2; }

    auto issueB = [&](int t){
        int bb = t % 3;
        #pragma unroll
        for (int i=0;i<4;i++){
            int idx = tid + i*256;
            cp16(&Btf[bb*4352 + (idx>>5)*136 + ((idx&31)<<2)],
                 Bg + ((size_t)t*32 + (idx>>5))*DHEAD + ((idx&31)<<2));
        }
        asm volatile("cp.async.commit_group;\n" ::: "memory");
    };

    float4 ra[2][4];
    auto ldgA = [&](int t){
        #pragma unroll
        for (int i=0;i<4;i++)
            ra[t&1][i] = *reinterpret_cast<const float4*>(Ag + (size_t)crow[i]*S_LEN + t*32 + ckk[i]);
    };
    auto xform = [&](int t){
        int ab = t & 1;
        #pragma unroll
        for (int i=0;i<4;i++){
            float M = sM[crow[i]], inv = sI[crow[i]];
            float4 v = ra[ab][i];
            float4 p;
            p.x = __expf(v.x - M)*inv;
            p.y = __expf(v.y - M)*inv;
            p.z = __expf(v.z - M)*inv;
            p.w = __expf(v.w - M)*inv;
            *reinterpret_cast<uint4*>(&Atf[ab*4608 + crow[i]*36 + ckk[i]]) =
                make_uint4(f2tf(p.x), f2tf(p.y), f2tf(p.z), f2tf(p.w));
            *reinterpret_cast<float4*>(Ag + (size_t)crow[i]*S_LEN + t*32 + ckk[i]) = p;
        }
    };

    float acc[4][4][4];
    #pragma unroll
    for (int i=0;i<4;i++)
        #pragma unroll
        for (int j=0;j<4;j++)
            #pragma unroll
            for (int r=0;r<4;r++) acc[i][j][r]=0.f;

    issueB(0);
    ldgA(0);
    issueB(1);
    ldgA(1);
    __syncthreads();
    xform(0);

    for (int kt=0; kt<nkt; kt++){
        asm volatile("cp.async.wait_group 0;\n" ::: "memory");
        __syncthreads();
        if (kt+2 < nkt){
            issueB(kt+2);
            ldgA(kt+2);
        }
        if (kt+1 < nkt) xform(kt+1);

        const uint32_t* Ah = Atf + (kt&1)*4608;
        const uint32_t* Bh = Btf + (kt%3)*4352;
        #pragma unroll
        for (int ks=0; ks<4; ks++){
            const int kb = ks*8;
            uint32_t ah[4][4], bh[4][2];
            #pragma unroll
            for (int mt=0; mt<4; mt++){
                int base = (wm*64 + mt*16 + rl)*36 + kb + cl;
                ah[mt][0]=Ah[base];     ah[mt][1]=Ah[base+288];
                ah[mt][2]=Ah[base+4];   ah[mt][3]=Ah[base+292];
            }
            #pragma unroll
            for (int nt=0; nt<4; nt++){
                int base = (kb + cl)*136 + wn*32 + nt*8 + rl;
                bh[nt][0]=Bh[base]; bh[nt][1]=Bh[base+544];
            }
            #pragma unroll
            for (int mt=0; mt<4; mt++)
                #pragma unroll
                for (int nt=0; nt<4; nt++)
                    mma8(acc[mt][nt], ah[mt], bh[nt]);
        }
    }

    const int b = z >> 3, h = z & 7;
    #pragma unroll
    for (int mt=0; mt<4; mt++){
        #pragma unroll
        for (int nt=0; nt<4; nt++){
            int row0 = mblk + wm*64 + mt*16 + rl;
            int col  = wn*32 + nt*8 + 2*cl;
            #pragma unroll
            for (int h2=0; h2<2; h2++){
                int row = row0 + h2*8;
                *reinterpret_cast<uint2*>(Dst + ((size_t)b*S_LEN + row)*FDIM + h*DHEAD + col)
                    = make_uint2(f2tf(acc[mt][nt][h2*2+0]), f2tf(acc[mt][nt][h2*2+1]));
            }
        }
    }
}

// ---------------- launch ----------------
extern "C" void kernel_launch(void* const* d_in, const int* in_sizes, int n_in,
                              void* d_out, int out_size)
{
    (void)in_sizes; (void)n_in; (void)out_size;
    const float* x  = (const float*)d_in[0];
    const float* wq = (const float*)d_in[1];
    const float* bq = (const float*)d_in[2];
    const float* uq = (const float*)d_in[3];
    const float* wk = (const float*)d_in[4];
    const float* bk = (const float*)d_in[5];
    const float* uk = (const float*)d_in[6];
    const float* wv = (const float*)d_in[7];
    const float* bv = (const float*)d_in[8];
    const float* uv = (const float*)d_in[9];
    const float* wo = (const float*)d_in[10];
    const float* bo = (const float*)d_in[11];
    const float* uo = (const float*)d_in[12];
    const float* gm = (const float*)d_in[13];

    float* out  = (float*)d_out;
    float* attn = out + (size_t)NTOK*FDIM;

    uint32_t *pxtf,*pwtf,*pvh,*pctxh;
    uint16_t *pxbh,*pxbl,*pwth,*pwtl,*pqkh,*pqkl;
    float *psig;
    cudaGetSymbolAddress((void**)&pxtf,  g_xtf);
    cudaGetSymbolAddress((void**)&pxbh,  g_xbh);
    cudaGetSymbolAddress((void**)&pxbl,  g_xbl);
    cudaGetSymbolAddress((void**)&pwtf,  g_wtf);
    cudaGetSymbolAddress((void**)&pwth,  g_wth);
    cudaGetSymbolAddress((void**)&pwtl,  g_wtl);
    cudaGetSymbolAddress((void**)&pqkh,  g_qkh);
    cudaGetSymbolAddress((void**)&pqkl,  g_qkl);
    cudaGetSymbolAddress((void**)&pvh,   g_vh);
    cudaGetSymbolAddress((void**)&pctxh, g_ctxh);
    cudaGetSymbolAddress((void**)&psig,  g_sig);

    cudaFuncSetAttribute(gemm_bf3<0>, cudaFuncAttributeMaxDynamicSharedMemorySize, 81920);
    cudaFuncSetAttribute(gemm_bf3<1>, cudaFuncAttributeMaxDynamicSharedMemorySize, 81920);
    cudaFuncSetAttribute(gemm_tf<1>,  cudaFuncAttributeMaxDynamicSharedMemorySize, 71680);
    cudaFuncSetAttribute(gemm_tf<3>,  cudaFuncAttributeMaxDynamicSharedMemorySize, 71680);
    cudaFuncSetAttribute(gemm_av,     cudaFuncAttributeMaxDynamicSharedMemorySize, 89088);

    // conversions + spectral norms
    k_conv_x<<<(NTOK*FDIM/4)/256,256>>>((const float4*)x,(uint4*)pxtf,(uint2*)pxbh,(uint2*)pxbl);
    k_conv_w<<<2*1024,256>>>((const float4*)wv,(const float4*)wo,(uint4*)pwtf);
    k_transp<<<dim3(32,32,2),256>>>(wq, wk, pwth, pwtl);
    k_sigma_v<<<dim3(128,4),256>>>(wq,wk,wv,wo, uq,uk,uv,uo);
    k_sigma_s<<<dim3(4,4),256>>>(wq,wk,wv,wo);
    k_sigma_fin<<<4,256>>>();

    // q,k projections (bf16x3, z=2): q = x @ wq^T^T via C = A B^T with B=wq^T
    gemm_bf3<1><<<dim3(8,64,2),256,81920>>>(pxbh, pxbl, pwth, pwtl,
        nullptr, pqkh, pqkl, FDIM, FDIM, FDIM, psig, bq, bk);

    // v projection (tf32 x1)
    gemm_tf<1><<<dim3(8,64,1),256,71680>>>(pxtf, pwtf, nullptr, pvh,
        FDIM, FDIM, FDIM, psig+2, bv, nullptr, nullptr);

    // logits = q k^T (bf16x3) + stats
    gemm_bf3<0><<<dim3(16,16,32),256,81920>>>(pqkh, pqkl, pqkh+QSZ, pqkl+QSZ,
        attn, nullptr, nullptr, DHEAD, DHEAD, DHEAD, nullptr, nullptr, nullptr);
    k_merge<<<(ZTOT*S_LEN)/256,256>>>();

    // ctx = softmax(logits) @ v, probs in place
    gemm_av<<<dim3(1,16,32),256,89088>>>(attn, pvh, pctxh);

    // out = x + (ctx @ wo + bo) * gamma
    gemm_tf<3><<<dim3(8,64,1),256,71680>>>(pctxh, pwtf+WSZE, out, nullptr,
        FDIM, FDIM, FDIM, psig, bo, x, gm);
}